// round 12
// baseline (speedup 1.0000x reference)
#include <cuda_runtime.h>
#include <cuda_bf16.h>
#include <cstdint>
#include <math.h>

// Problem dims
#define BB  128
#define TT  31
#define TP1 32
#define EE  512
#define HH  512
#define H4  2048
#define VV  10000
#define AA  2048
#define MTOT 4096   // (T+1)*B rows
#define LDP 2560    // fused precompute row stride (AA + EE)

// ---------------- device scratch (static, no allocs) ----------------
__device__ float g_c    [BB*HH];
__device__ float g_pre  [MTOT*LDP];    // [t][b][0:2048]=attnx, [2048:2560]=attdx (x2 acc target)
__device__ float g_alogp[4*BB*AA];     // attn-logit split-K partials (z=4)
__device__ float g_gp   [8*BB*H4];     // gate partials (z 0..3 = x-part, 4..7 = h-part)
__device__ float g_bias2560[LDP];      // [0]*2048 | b_attd

// bf16 split activation buffers
__device__ __nv_bfloat16 g_xs_hi [MTOT*EE], g_xs_lo [MTOT*EE];
__device__ __nv_bfloat16 g_hid_hi[MTOT*HH], g_hid_lo[MTOT*HH];
__device__ __nv_bfloat16 g_xh_hi [BB*1024], g_xh_lo [BB*1024];   // [x2|h] (x part used at t=0 only)
__device__ __nv_bfloat16 g_att_hi[BB*AA],   g_att_lo[BB*AA];

// bf16 split weights
__device__ __nv_bfloat16 g_Woh[VV*HH],   g_Wol[VV*HH];     // W_out
__device__ __nv_bfloat16 g_Wprh[LDP*EE], g_Wprl[LDP*EE];   // [W_attn_x ; W_attd_x] fused (rows 0..2047, 2048..2559)
__device__ __nv_bfloat16 g_Wn2h[AA*HH],  g_Wn2l[AA*HH];    // W_attn h-part
__device__ __nv_bfloat16 g_Wd2h[EE*AA],  g_Wd2l[EE*AA];    // W_attd a-part
__device__ __nv_bfloat16 g_Wch[H4*1024], g_Wcl[H4*1024];   // [W_ih|W_hh]

// ================= warp-MMA helpers (sm_80+ baseline PTX only) =================
__device__ __forceinline__ uint32_t smem_u32(const void* p) {
    uint32_t a;
    asm("{ .reg .u64 t; cvta.to.shared.u64 t, %1; cvt.u32.u64 %0, t; }" : "=r"(a) : "l"(p));
    return a;
}
__device__ __forceinline__ uint32_t sw128(uint32_t b) { return b ^ ((b >> 3) & 0x70); }

__device__ __forceinline__ void ldsm_x4(uint32_t* r, uint32_t addr) {
    asm volatile("ldmatrix.sync.aligned.m8n8.x4.shared.b16 {%0,%1,%2,%3}, [%4];"
                 : "=r"(r[0]), "=r"(r[1]), "=r"(r[2]), "=r"(r[3]) : "r"(addr));
}
__device__ __forceinline__ void ldsm_x2(uint32_t* r, uint32_t addr) {
    asm volatile("ldmatrix.sync.aligned.m8n8.x2.shared.b16 {%0,%1}, [%2];"
                 : "=r"(r[0]), "=r"(r[1]) : "r"(addr));
}
__device__ __forceinline__ void mma16816(float* d, const uint32_t* a, const uint32_t* b) {
    asm volatile("mma.sync.aligned.m16n8k16.row.col.f32.bf16.bf16.f32 "
                 "{%0,%1,%2,%3}, {%4,%5,%6,%7}, {%8,%9}, {%0,%1,%2,%3};"
                 : "+f"(d[0]), "+f"(d[1]), "+f"(d[2]), "+f"(d[3])
                 : "r"(a[0]), "r"(a[1]), "r"(a[2]), "r"(a[3]), "r"(b[0]), "r"(b[1]));
}
__device__ __forceinline__ void cpasync16(uint32_t dst, const void* src, int sz) {
    asm volatile("cp.async.cg.shared.global [%0], [%1], 16, %2;"
                 :: "r"(dst), "l"(src), "r"(sz));
}
#define CP_COMMIT() asm volatile("cp.async.commit_group;" ::: "memory")
#define CP_WAIT1()  asm volatile("cp.async.wait_group 1;" ::: "memory")
#define CP_WAIT0()  asm volatile("cp.async.wait_group 0;" ::: "memory")

__device__ __forceinline__ void split_write(float x, __nv_bfloat16* hi, __nv_bfloat16* lo, size_t i) {
    __nv_bfloat16 h = __float2bfloat16(x);
    hi[i] = h;
    lo[i] = __float2bfloat16(x - __bfloat162float(h));
}
__device__ __forceinline__ float sigmoidf_(float x) {
    return 1.0f / (1.0f + expf(-x));
}

// ============ MMA core: 128x128 tile over loaded smem (shared by all variants) ============
// smem layout: Ahi@0, Alo@16K, Bhi@32K, Blo@48K
__device__ __forceinline__ void mma_passes(uint32_t sb, float acc[4][4][4],
                                           int warp_m, int warp_n, int lane)
{
    #pragma unroll
    for (int pass = 0; pass < 3; pass++) {
        const uint32_t abase = sb + ((pass == 2) ? 16384 : 0);
        const uint32_t bbase = sb + 32768 + ((pass == 1) ? 16384 : 0);
        #pragma unroll
        for (int kk = 0; kk < 4; kk++) {
            uint32_t afr[4][4];
            #pragma unroll
            for (int mt = 0; mt < 4; mt++) {
                int row = warp_m * 64 + mt * 16 + (lane & 15);
                int kb  = kk * 32 + ((lane >> 4) << 4);
                ldsm_x4(afr[mt], abase + sw128(row * 128 + kb));
            }
            uint32_t bfr[4][2];
            #pragma unroll
            for (int nt = 0; nt < 4; nt++) {
                int row = warp_n * 32 + nt * 8 + (lane & 7);
                int kb  = kk * 32 + (((lane >> 3) & 1) << 4);
                ldsm_x2(bfr[nt], bbase + sw128(row * 128 + kb));
            }
            #pragma unroll
            for (int mt = 0; mt < 4; mt++)
                #pragma unroll
                for (int nt = 0; nt < 4; nt++)
                    mma16816(acc[mt][nt], afr[mt], bfr[nt]);
        }
    }
}

__device__ __forceinline__ void load_bf16_tile(char* smem, uint32_t dstbase,
                                               const __nv_bfloat16* __restrict__ src,
                                               int rowbase, int ld, int kofs, int tid)
{
    #pragma unroll
    for (int j = 0; j < 4; j++) {
        int v = tid + j * 256;
        int row = v >> 3, c8 = v & 7;
        uint4 val = *(const uint4*)(src + (size_t)(rowbase + row) * ld + kofs + c8 * 8);
        *(uint4*)(smem + dstbase + sw128(row * 128 + c8 * 16)) = val;
    }
}

// fp32 A tile -> hi/lo bf16 smem tiles (on-the-fly split)
__device__ __forceinline__ void load_f32_tile_split(char* smem,
                                                    const float* __restrict__ src,
                                                    int ld, int kofs, int tid)
{
    #pragma unroll
    for (int j = 0; j < 4; j++) {
        int v = tid + j * 256;
        int row = v >> 3, c8 = v & 7;
        const float* sp = src + (size_t)row * ld + kofs + c8 * 8;
        float4 f0 = *(const float4*)sp;
        float4 f1 = *(const float4*)(sp + 4);
        float fv[8] = {f0.x, f0.y, f0.z, f0.w, f1.x, f1.y, f1.z, f1.w};
        alignas(16) __nv_bfloat16 hb[8];
        alignas(16) __nv_bfloat16 lb[8];
        #pragma unroll
        for (int q = 0; q < 8; q++) {
            hb[q] = __float2bfloat16(fv[q]);
            lb[q] = __float2bfloat16(fv[q] - __bfloat162float(hb[q]));
        }
        uint32_t off = sw128(row * 128 + c8 * 16);
        *(uint4*)(smem + off)         = *(uint4*)hb;
        *(uint4*)(smem + 16384 + off) = *(uint4*)lb;
    }
}

// ============ big warp-MMA split-bf16 GEMM, cp.async double-buffered ============
__global__ void __launch_bounds__(256, 1)
gemm_mma_kernel(const __nv_bfloat16* __restrict__ Ahi,
                const __nv_bfloat16* __restrict__ Alo,
                const __nv_bfloat16* __restrict__ Bhi,
                const __nv_bfloat16* __restrict__ Blo,
                const float* __restrict__ bias,
                float* __restrict__ C, int ldc, int Ntot, int K)
{
    extern __shared__ char smem[];
    const uint32_t sb = smem_u32(smem);
    const int tid = threadIdx.x;
    const int wid = tid >> 5;
    const int lane = tid & 31;
    const int warp_m = wid & 1;
    const int warp_n = wid >> 1;
    const int bm = blockIdx.y * 128;
    const int bn = blockIdx.x * 128;

    float acc[4][4][4];
    #pragma unroll
    for (int i = 0; i < 4; i++)
        #pragma unroll
        for (int j = 0; j < 4; j++)
            #pragma unroll
            for (int r = 0; r < 4; r++) acc[i][j][r] = 0.0f;

    const __nv_bfloat16* srcs[4] = {Ahi, Alo, Bhi, Blo};
    const int nchunks = K >> 6;

    auto issue = [&](int kc, int buf) {
        const uint32_t bufbase = sb + buf * 65536;
        #pragma unroll
        for (int t = 0; t < 4; t++) {
            const __nv_bfloat16* src = srcs[t];
            const uint32_t dstbase = bufbase + t * 16384;
            #pragma unroll
            for (int j = 0; j < 4; j++) {
                int v = tid + j * 256;
                int row = v >> 3, c8 = v & 7;
                int sz = 16;
                const __nv_bfloat16* sp;
                if (t < 2) {
                    sp = src + (size_t)(bm + row) * K + kc * 64 + c8 * 8;
                } else {
                    int gn = bn + row;
                    if (gn >= Ntot) { gn = 0; sz = 0; }
                    sp = src + (size_t)gn * K + kc * 64 + c8 * 8;
                }
                cpasync16(dstbase + sw128(row * 128 + c8 * 16), sp, sz);
            }
        }
    };

    issue(0, 0);
    CP_COMMIT();

    for (int kc = 0; kc < nchunks; kc++) {
        const int buf = kc & 1;
        if (kc + 1 < nchunks) {
            issue(kc + 1, buf ^ 1);
            CP_COMMIT();
            CP_WAIT1();
        } else {
            CP_WAIT0();
        }
        __syncthreads();
        mma_passes(sb + buf * 65536, acc, warp_m, warp_n, lane);
        __syncthreads();
    }

    const int gid = lane >> 2;
    const int tg  = lane & 3;
    #pragma unroll
    for (int mt = 0; mt < 4; mt++) {
        int row0 = bm + warp_m * 64 + mt * 16 + gid;
        #pragma unroll
        for (int nt = 0; nt < 4; nt++) {
            int col = bn + warp_n * 32 + nt * 8 + tg * 2;
            if (col < Ntot) {
                float b0 = bias ? bias[col] : 0.0f;
                float b1 = bias ? bias[col + 1] : 0.0f;
                float2 v0 = make_float2(acc[mt][nt][0] + b0, acc[mt][nt][1] + b1);
                float2 v1 = make_float2(acc[mt][nt][2] + b0, acc[mt][nt][3] + b1);
                *(float2*)(C + (size_t)row0 * ldc + col) = v0;
                *(float2*)(C + (size_t)(row0 + 8) * ldc + col) = v1;
            }
        }
    }
}

// ============ step GEMM: M=128, bf16 A, split-K, fp32 partials (t=0 gates) ============
__global__ void __launch_bounds__(256, 1)
gemm_mma_step(const __nv_bfloat16* __restrict__ Ahi,
              const __nv_bfloat16* __restrict__ Alo, int lda,
              const __nv_bfloat16* __restrict__ Bhi,
              const __nv_bfloat16* __restrict__ Blo, int ldb,
              float* __restrict__ Cpart, int N, size_t pstride, int Kchunk)
{
    extern __shared__ char smem[];
    const uint32_t sb = smem_u32(smem);
    const int tid = threadIdx.x;
    const int wid = tid >> 5;
    const int lane = tid & 31;
    const int warp_m = wid & 1;
    const int warp_n = wid >> 1;
    const int bn = blockIdx.x * 128;
    const int kb = blockIdx.z * Kchunk;
    float* C = Cpart + (size_t)blockIdx.z * pstride;

    float acc[4][4][4];
    #pragma unroll
    for (int i = 0; i < 4; i++)
        #pragma unroll
        for (int j = 0; j < 4; j++)
            #pragma unroll
            for (int r = 0; r < 4; r++) acc[i][j][r] = 0.0f;

    const int nchunks = Kchunk >> 6;
    for (int kc = 0; kc < nchunks; kc++) {
        if (kc > 0) __syncthreads();
        load_bf16_tile(smem, 0,     Ahi, 0,  lda, kb + kc * 64, tid);
        load_bf16_tile(smem, 16384, Alo, 0,  lda, kb + kc * 64, tid);
        load_bf16_tile(smem, 32768, Bhi, bn, ldb, kb + kc * 64, tid);
        load_bf16_tile(smem, 49152, Blo, bn, ldb, kb + kc * 64, tid);
        __syncthreads();
        mma_passes(sb, acc, warp_m, warp_n, lane);
    }

    const int gid = lane >> 2;
    const int tg  = lane & 3;
    #pragma unroll
    for (int mt = 0; mt < 4; mt++) {
        int row0 = warp_m * 64 + mt * 16 + gid;
        #pragma unroll
        for (int nt = 0; nt < 4; nt++) {
            int col = bn + warp_n * 32 + nt * 8 + tg * 2;
            *(float2*)(C + (size_t)row0 * N + col) =
                make_float2(acc[mt][nt][0], acc[mt][nt][1]);
            *(float2*)(C + (size_t)(row0 + 8) * N + col) =
                make_float2(acc[mt][nt][2], acc[mt][nt][3]);
        }
    }
}

// ============ fused step link 1: alog (blocks 0..63) + gates_h (blocks 64..127) ============
// A = h (xh+512) both.  N = 2048 both.  Kchunk=128, kz = id&3, ntile = id>>2.
__global__ void __launch_bounds__(256, 1)
fused_alog_gatesh(const __nv_bfloat16* __restrict__ Ahi,
                  const __nv_bfloat16* __restrict__ Alo,
                  const __nv_bfloat16* __restrict__ B1hi,
                  const __nv_bfloat16* __restrict__ B1lo,   // Wn2, ldb 512
                  const __nv_bfloat16* __restrict__ B2hi,
                  const __nv_bfloat16* __restrict__ B2lo,   // Wch+512, ldb 1024
                  float* __restrict__ C1,                    // alogp
                  float* __restrict__ C2)                    // gp + 4*BB*H4
{
    extern __shared__ char smem[];
    const uint32_t sb = smem_u32(smem);
    const int tid = threadIdx.x;
    const int wid = tid >> 5;
    const int lane = tid & 31;
    const int warp_m = wid & 1;
    const int warp_n = wid >> 1;
    const bool isg = blockIdx.x >= 64;
    const int id = blockIdx.x & 63;
    const int bn = (id >> 2) * 128;
    const int kb = (id & 3) * 128;
    const __nv_bfloat16* Bhi = isg ? B2hi : B1hi;
    const __nv_bfloat16* Blo = isg ? B2lo : B1lo;
    const int ldb = isg ? 1024 : 512;
    float* C = (isg ? C2 : C1) + (size_t)(id & 3) * BB * 2048;

    float acc[4][4][4];
    #pragma unroll
    for (int i = 0; i < 4; i++)
        #pragma unroll
        for (int j = 0; j < 4; j++)
            #pragma unroll
            for (int r = 0; r < 4; r++) acc[i][j][r] = 0.0f;

    #pragma unroll
    for (int kc = 0; kc < 2; kc++) {
        if (kc > 0) __syncthreads();
        load_bf16_tile(smem, 0,     Ahi, 0,  1024, kb + kc * 64, tid);
        load_bf16_tile(smem, 16384, Alo, 0,  1024, kb + kc * 64, tid);
        load_bf16_tile(smem, 32768, Bhi, bn, ldb,  kb + kc * 64, tid);
        load_bf16_tile(smem, 49152, Blo, bn, ldb,  kb + kc * 64, tid);
        __syncthreads();
        mma_passes(sb, acc, warp_m, warp_n, lane);
    }

    const int gid = lane >> 2;
    const int tg  = lane & 3;
    #pragma unroll
    for (int mt = 0; mt < 4; mt++) {
        int row0 = warp_m * 64 + mt * 16 + gid;
        #pragma unroll
        for (int nt = 0; nt < 4; nt++) {
            int col = bn + warp_n * 32 + nt * 8 + tg * 2;
            *(float2*)(C + (size_t)row0 * 2048 + col) =
                make_float2(acc[mt][nt][0], acc[mt][nt][1]);
            *(float2*)(C + (size_t)(row0 + 8) * 2048 + col) =
                make_float2(acc[mt][nt][2], acc[mt][nt][3]);
        }
    }
}

// ============ x2 GEMM: atomicAdd into fp32 attdx slice (combine eliminated) ============
__global__ void __launch_bounds__(256, 1)
gemm_x2_atomic(const __nv_bfloat16* __restrict__ Ahi,
               const __nv_bfloat16* __restrict__ Alo,     // att, lda AA
               const __nv_bfloat16* __restrict__ Bhi,
               const __nv_bfloat16* __restrict__ Blo,     // Wd2, ldb AA
               float* __restrict__ C, int ldc)            // g_pre slice +2048, ldc LDP
{
    extern __shared__ char smem[];
    const uint32_t sb = smem_u32(smem);
    const int tid = threadIdx.x;
    const int wid = tid >> 5;
    const int lane = tid & 31;
    const int warp_m = wid & 1;
    const int warp_n = wid >> 1;
    const int bn = blockIdx.x * 128;
    const int kb = blockIdx.z * 128;

    float acc[4][4][4];
    #pragma unroll
    for (int i = 0; i < 4; i++)
        #pragma unroll
        for (int j = 0; j < 4; j++)
            #pragma unroll
            for (int r = 0; r < 4; r++) acc[i][j][r] = 0.0f;

    #pragma unroll
    for (int kc = 0; kc < 2; kc++) {
        if (kc > 0) __syncthreads();
        load_bf16_tile(smem, 0,     Ahi, 0,  AA, kb + kc * 64, tid);
        load_bf16_tile(smem, 16384, Alo, 0,  AA, kb + kc * 64, tid);
        load_bf16_tile(smem, 32768, Bhi, bn, AA, kb + kc * 64, tid);
        load_bf16_tile(smem, 49152, Blo, bn, AA, kb + kc * 64, tid);
        __syncthreads();
        mma_passes(sb, acc, warp_m, warp_n, lane);
    }

    const int gid = lane >> 2;
    const int tg  = lane & 3;
    #pragma unroll
    for (int mt = 0; mt < 4; mt++) {
        int row0 = warp_m * 64 + mt * 16 + gid;
        #pragma unroll
        for (int nt = 0; nt < 4; nt++) {
            int col = bn + warp_n * 32 + nt * 8 + tg * 2;
            atomicAdd(C + (size_t)row0 * ldc + col,       acc[mt][nt][0]);
            atomicAdd(C + (size_t)row0 * ldc + col + 1,   acc[mt][nt][1]);
            atomicAdd(C + (size_t)(row0 + 8) * ldc + col,     acc[mt][nt][2]);
            atomicAdd(C + (size_t)(row0 + 8) * ldc + col + 1, acc[mt][nt][3]);
        }
    }
}

// ============ gates x-part GEMM: A from fp32 (split on load), partials z 0..3 ============
__global__ void __launch_bounds__(256, 1)
gemm_gates_f32a(const float* __restrict__ Af, int ldaf,    // x2 fp32 (g_pre slice +2048)
                const __nv_bfloat16* __restrict__ Bhi,
                const __nv_bfloat16* __restrict__ Blo,     // Wch/Wcl, ldb 1024
                float* __restrict__ Cpart)                 // gp, pstride BB*H4
{
    extern __shared__ char smem[];
    const uint32_t sb = smem_u32(smem);
    const int tid = threadIdx.x;
    const int wid = tid >> 5;
    const int lane = tid & 31;
    const int warp_m = wid & 1;
    const int warp_n = wid >> 1;
    const int bn = blockIdx.x * 128;
    const int kb = blockIdx.z * 128;
    float* C = Cpart + (size_t)blockIdx.z * BB * H4;

    float acc[4][4][4];
    #pragma unroll
    for (int i = 0; i < 4; i++)
        #pragma unroll
        for (int j = 0; j < 4; j++)
            #pragma unroll
            for (int r = 0; r < 4; r++) acc[i][j][r] = 0.0f;

    #pragma unroll
    for (int kc = 0; kc < 2; kc++) {
        if (kc > 0) __syncthreads();
        load_f32_tile_split(smem, Af, ldaf, kb + kc * 64, tid);
        load_bf16_tile(smem, 32768, Bhi, bn, 1024, kb + kc * 64, tid);
        load_bf16_tile(smem, 49152, Blo, bn, 1024, kb + kc * 64, tid);
        __syncthreads();
        mma_passes(sb, acc, warp_m, warp_n, lane);
    }

    const int gid = lane >> 2;
    const int tg  = lane & 3;
    #pragma unroll
    for (int mt = 0; mt < 4; mt++) {
        int row0 = warp_m * 64 + mt * 16 + gid;
        #pragma unroll
        for (int nt = 0; nt < 4; nt++) {
            int col = bn + warp_n * 32 + nt * 8 + tg * 2;
            *(float2*)(C + (size_t)row0 * H4 + col) =
                make_float2(acc[mt][nt][0], acc[mt][nt][1]);
            *(float2*)(C + (size_t)(row0 + 8) * H4 + col) =
                make_float2(acc[mt][nt][2], acc[mt][nt][3]);
        }
    }
}

// ================= setup / pointwise kernels =================

// xs split + xh init + c init, one kernel
__global__ void build_xs_kernel(const float* __restrict__ features,
                                const int*   __restrict__ captions,
                                const float* __restrict__ table,
                                __nv_bfloat16* __restrict__ hi,
                                __nv_bfloat16* __restrict__ lo,
                                __nv_bfloat16* __restrict__ xh_hi,
                                __nv_bfloat16* __restrict__ xh_lo,
                                float* __restrict__ c)
{
    int idx = blockIdx.x * blockDim.x + threadIdx.x;
    if (idx < MTOT * EE) {
        int e = idx % EE;
        int b = (idx / EE) % BB;
        int t = idx / (EE * BB);
        float v;
        if (t == 0) v = features[b * EE + e];
        else {
            int tok = captions[b * TT + (t - 1)];
            v = table[tok * EE + e];
        }
        split_write(v, hi, lo, idx);
        return;
    }
    idx -= MTOT * EE;
    if (idx < BB * 1024) {
        int b = idx / 1024, k = idx % 1024;
        float v = (k < 512) ? features[b * 512 + k] : 0.0f;
        split_write(v, xh_hi, xh_lo, idx);
        return;
    }
    idx -= BB * 1024;
    if (idx < BB * HH) c[idx] = 0.0f;
}

// all weight splits + fused precompute weight + wcat + bias2560, one kernel
#define S1SZ (AA*EE)      // W_attn x-part -> Wpr rows 0..2047
#define S2SZ (AA*HH)      // W_attn h-part -> Wn2
#define S3SZ (EE*EE)      // W_attd x-part -> Wpr rows 2048..2559
#define S4SZ (EE*AA)      // W_attd a-part -> Wd2
#define S5SZ (VV*HH)      // W_out -> Wo
#define S6SZ (H4*1024)    // Wcat
#define S7SZ (LDP)        // bias2560
__global__ void convert_all_kernel(const float* __restrict__ W_attn,
                                   const float* __restrict__ W_attd,
                                   const float* __restrict__ W_out,
                                   const float* __restrict__ Wih,
                                   const float* __restrict__ Whh,
                                   const float* __restrict__ b_attd,
                                   __nv_bfloat16* __restrict__ Wprh, __nv_bfloat16* __restrict__ Wprl,
                                   __nv_bfloat16* __restrict__ Wn2h, __nv_bfloat16* __restrict__ Wn2l,
                                   __nv_bfloat16* __restrict__ Wd2h, __nv_bfloat16* __restrict__ Wd2l,
                                   __nv_bfloat16* __restrict__ Woh,  __nv_bfloat16* __restrict__ Wol,
                                   __nv_bfloat16* __restrict__ Wch,  __nv_bfloat16* __restrict__ Wcl,
                                   float* __restrict__ bias2560)
{
    int idx = blockIdx.x * blockDim.x + threadIdx.x;
    if (idx < S1SZ) {
        int r = idx / EE, cc = idx % EE;
        split_write(W_attn[(size_t)r * 1024 + cc], Wprh, Wprl, idx);
        return;
    }
    idx -= S1SZ;
    if (idx < S2SZ) {
        int r = idx / HH, cc = idx % HH;
        split_write(W_attn[(size_t)r * 1024 + EE + cc], Wn2h, Wn2l, idx);
        return;
    }
    idx -= S2SZ;
    if (idx < S3SZ) {
        int r = idx / EE, cc = idx % EE;
        split_write(W_attd[(size_t)r * 2560 + cc], Wprh, Wprl, (size_t)(2048 + r) * EE + cc);
        return;
    }
    idx -= S3SZ;
    if (idx < S4SZ) {
        int r = idx / AA, cc = idx % AA;
        split_write(W_attd[(size_t)r * 2560 + EE + cc], Wd2h, Wd2l, idx);
        return;
    }
    idx -= S4SZ;
    if (idx < S5SZ) {
        split_write(W_out[idx], Woh, Wol, idx);
        return;
    }
    idx -= S5SZ;
    if (idx < S6SZ) {
        int n = idx / 1024, k = idx % 1024;
        float v = (k < 512) ? Wih[n * 512 + k] : Whh[n * 512 + (k - 512)];
        split_write(v, Wch, Wcl, idx);
        return;
    }
    idx -= S6SZ;
    if (idx < S7SZ) {
        bias2560[idx] = (idx < AA) ? 0.0f : b_attd[idx - AA];
    }
}

// softmax over 2048 (4 partials + attnx + bias), attend, write bf16 hi/lo
__global__ void softmax_attend_kernel(const float* __restrict__ parts,
                                      const float* __restrict__ attnx, // g_pre slice, ld LDP
                                      const float* __restrict__ b_attn,
                                      const float* __restrict__ cnn,
                                      __nv_bfloat16* __restrict__ att_hi,
                                      __nv_bfloat16* __restrict__ att_lo)
{
    const int b = blockIdx.x;
    const int tid = threadIdx.x;     // 256
    __shared__ float red[256];

    float v[8];
    float mx = -1e30f;
    #pragma unroll
    for (int j = 0; j < 8; j++) {
        int col = tid + j * 256;
        size_t o = (size_t)b * AA + col;
        float s = attnx[(size_t)b * LDP + col] + b_attn[col];
        #pragma unroll
        for (int p = 0; p < 4; p++) s += parts[(size_t)p * BB * AA + o];
        v[j] = s;
        mx = fmaxf(mx, s);
    }
    red[tid] = mx;
    __syncthreads();
    for (int s = 128; s > 0; s >>= 1) {
        if (tid < s) red[tid] = fmaxf(red[tid], red[tid + s]);
        __syncthreads();
    }
    mx = red[0];
    __syncthreads();

    float sum = 0.0f;
    #pragma unroll
    for (int j = 0; j < 8; j++) { v[j] = expf(v[j] - mx); sum += v[j]; }
    red[tid] = sum;
    __syncthreads();
    for (int s = 128; s > 0; s >>= 1) {
        if (tid < s) red[tid] += red[tid + s];
        __syncthreads();
    }
    float inv = 1.0f / red[0];

    #pragma unroll
    for (int j = 0; j < 8; j++) {
        int col = tid + j * 256;
        size_t o = (size_t)b * AA + col;
        split_write(cnn[o] * v[j] * inv, att_hi, att_lo, o);
    }
}

// LSTM pointwise: combine 8 gate partials + biases; update c; write h
__global__ void lstm_pointwise_kernel(const float* __restrict__ gp,
                                      const float* __restrict__ b_ih,
                                      const float* __restrict__ b_hh,
                                      __nv_bfloat16* __restrict__ xh_hi,
                                      __nv_bfloat16* __restrict__ xh_lo,
                                      float* __restrict__ c,
                                      __nv_bfloat16* __restrict__ hid_hi,
                                      __nv_bfloat16* __restrict__ hid_lo)
{
    int idx = blockIdx.x * blockDim.x + threadIdx.x;
    if (idx >= BB * HH) return;
    int b = idx / HH, n = idx % HH;
    float gi = b_ih[n]        + b_hh[n];
    float gf = b_ih[512 + n]  + b_hh[512 + n];
    float gg = b_ih[1024 + n] + b_hh[1024 + n];
    float go = b_ih[1536 + n] + b_hh[1536 + n];
    #pragma unroll
    for (int p = 0; p < 8; p++) {
        const float* base = gp + (size_t)p * BB * H4 + (size_t)b * H4;
        gi += base[n];
        gf += base[512 + n];
        gg += base[1024 + n];
        go += base[1536 + n];
    }
    gi = sigmoidf_(gi);
    gf = sigmoidf_(gf);
    gg = tanhf(gg);
    go = sigmoidf_(go);
    float cc = gf * c[idx] + gi * gg;
    float hh = go * tanhf(cc);
    c[idx] = cc;
    split_write(hh, xh_hi, xh_lo, (size_t)b * 1024 + 512 + n);
    split_write(hh, hid_hi, hid_lo, idx);
}

// ---------------- host ----------------

extern "C" void kernel_launch(void* const* d_in, const int* in_sizes, int n_in,
                              void* d_out, int out_size)
{
    const float* features = (const float*)d_in[0];
    const float* cnn      = (const float*)d_in[1];
    const int*   captions = (const int*)  d_in[2];
    const float* table    = (const float*)d_in[4];
    const float* W_ih     = (const float*)d_in[5];
    const float* W_hh     = (const float*)d_in[6];
    const float* b_ih     = (const float*)d_in[7];
    const float* b_hh     = (const float*)d_in[8];
    const float* W_attn   = (const float*)d_in[9];
    const float* b_attn   = (const float*)d_in[10];
    const float* W_attd   = (const float*)d_in[11];
    const float* b_attd   = (const float*)d_in[12];
    const float* W_out    = (const float*)d_in[13];
    const float* b_out    = (const float*)d_in[14];
    float* out = (float*)d_out;

    float *p_c, *p_pre, *p_alogp, *p_gp, *p_b2560;
    __nv_bfloat16 *p_xsh, *p_xsl, *p_hih, *p_hil, *p_xhh, *p_xhl, *p_ath, *p_atl,
                  *p_Woh, *p_Wol, *p_Wprh, *p_Wprl, *p_Wn2h, *p_Wn2l,
                  *p_Wd2h, *p_Wd2l, *p_Wch, *p_Wcl;
    cudaGetSymbolAddress((void**)&p_c,     g_c);
    cudaGetSymbolAddress((void**)&p_pre,   g_pre);
    cudaGetSymbolAddress((void**)&p_alogp, g_alogp);
    cudaGetSymbolAddress((void**)&p_gp,    g_gp);
    cudaGetSymbolAddress((void**)&p_b2560, g_bias2560);
    cudaGetSymbolAddress((void**)&p_xsh,   g_xs_hi);
    cudaGetSymbolAddress((void**)&p_xsl,   g_xs_lo);
    cudaGetSymbolAddress((void**)&p_hih,   g_hid_hi);
    cudaGetSymbolAddress((void**)&p_hil,   g_hid_lo);
    cudaGetSymbolAddress((void**)&p_xhh,   g_xh_hi);
    cudaGetSymbolAddress((void**)&p_xhl,   g_xh_lo);
    cudaGetSymbolAddress((void**)&p_ath,   g_att_hi);
    cudaGetSymbolAddress((void**)&p_atl,   g_att_lo);
    cudaGetSymbolAddress((void**)&p_Woh,   g_Woh);
    cudaGetSymbolAddress((void**)&p_Wol,   g_Wol);
    cudaGetSymbolAddress((void**)&p_Wprh,  g_Wprh);
    cudaGetSymbolAddress((void**)&p_Wprl,  g_Wprl);
    cudaGetSymbolAddress((void**)&p_Wn2h,  g_Wn2h);
    cudaGetSymbolAddress((void**)&p_Wn2l,  g_Wn2l);
    cudaGetSymbolAddress((void**)&p_Wd2h,  g_Wd2h);
    cudaGetSymbolAddress((void**)&p_Wd2l,  g_Wd2l);
    cudaGetSymbolAddress((void**)&p_Wch,   g_Wch);
    cudaGetSymbolAddress((void**)&p_Wcl,   g_Wcl);

    cudaFuncSetAttribute(gemm_mma_kernel,   cudaFuncAttributeMaxDynamicSharedMemorySize, 131072);
    cudaFuncSetAttribute(gemm_mma_step,     cudaFuncAttributeMaxDynamicSharedMemorySize, 65536);
    cudaFuncSetAttribute(fused_alog_gatesh, cudaFuncAttributeMaxDynamicSharedMemorySize, 65536);
    cudaFuncSetAttribute(gemm_x2_atomic,    cudaFuncAttributeMaxDynamicSharedMemorySize, 65536);
    cudaFuncSetAttribute(gemm_gates_f32a,   cudaFuncAttributeMaxDynamicSharedMemorySize, 65536);

    // ---- setup (2 kernels) ----
    {
        int total = MTOT * EE + BB * 1024 + BB * HH;
        build_xs_kernel<<<(total + 255) / 256, 256>>>(
            features, captions, table, p_xsh, p_xsl, p_xhh, p_xhl, p_c);
    }
    {
        long total = (long)S1SZ + S2SZ + S3SZ + S4SZ + S5SZ + S6SZ + S7SZ;
        convert_all_kernel<<<(int)((total + 255) / 256), 256>>>(
            W_attn, W_attd, W_out, W_ih, W_hh, b_attd,
            p_Wprh, p_Wprl, p_Wn2h, p_Wn2l, p_Wd2h, p_Wd2l,
            p_Woh, p_Wol, p_Wch, p_Wcl, p_b2560);
    }

    // ---- fused precompute: [attnx | attdx] = xs @ Wpr^T + [0|b_attd] ----
    gemm_mma_kernel<<<dim3(LDP / 128, MTOT / 128), 256, 131072>>>(
        p_xsh, p_xsl, p_Wprh, p_Wprl, p_b2560, p_pre, LDP, LDP, EE);

    // ---- t = 0: gates = [features|0] @ Wcat^T (z=8, bf16 A), LSTM ----
    gemm_mma_step<<<dim3(H4 / 128, 1, 8), 256, 65536>>>(
        p_xhh, p_xhl, 1024, p_Wch, p_Wcl, 1024, p_gp, H4, (size_t)BB * H4, 128);
    lstm_pointwise_kernel<<<(BB * HH + 255) / 256, 256>>>(
        p_gp, b_ih, b_hh, p_xhh, p_xhl, p_c, p_hih, p_hil);

    // ---- recurrent loop: 5 launches per step ----
    for (int t = 1; t <= TT; t++) {
        float* pre_t = p_pre + (size_t)t * BB * LDP;         // attnx @ +0, attdx/x2 @ +2048

        // (1) alog partials + gates_h partials, one launch (both need only h(t-1))
        fused_alog_gatesh<<<128, 256, 65536>>>(
            p_xhh + 512, p_xhl + 512,
            p_Wn2h, p_Wn2l, p_Wch + 512, p_Wcl + 512,
            p_alogp, p_gp + (size_t)4 * BB * H4);
        // (2) softmax + attend -> att bf16
        softmax_attend_kernel<<<BB, 256>>>(p_alogp, pre_t, b_attn, cnn, p_ath, p_atl);
        // (3) x2 = att @ Wd2^T, atomicAdd into fp32 attdx slice (becomes x2)
        gemm_x2_atomic<<<dim3(EE / 128, 1, 16), 256, 65536>>>(
            p_ath, p_atl, p_Wd2h, p_Wd2l, pre_t + 2048, LDP);
        // (4) gates x-part: x2(fp32) @ W_ih^T, A split on load (z 0..3)
        gemm_gates_f32a<<<dim3(H4 / 128, 1, 4), 256, 65536>>>(
            pre_t + 2048, LDP, p_Wch, p_Wcl, p_gp);
        // (5) LSTM pointwise (sums all 8 partials)
        lstm_pointwise_kernel<<<(BB * HH + 255) / 256, 256>>>(
            p_gp, b_ih, b_hh, p_xhh, p_xhl, p_c,
            p_hih + (size_t)t * BB * HH, p_hil + (size_t)t * BB * HH);
    }

    // ---- output projection: logits = hidden @ W_out^T + b_out ----
    gemm_mma_kernel<<<dim3((VV + 127) / 128, MTOT / 128), 256, 131072>>>(
        p_hih, p_hil, p_Woh, p_Wol, b_out, out, VV, VV, HH);
}

// round 13
// speedup vs baseline: 1.4926x; 1.4926x over previous
#include <cuda_runtime.h>
#include <cuda_bf16.h>
#include <cstdint>
#include <math.h>

// Problem dims
#define BB  128
#define TT  31
#define TP1 32
#define EE  512
#define HH  512
#define H4  2048
#define VV  10000
#define AA  2048
#define MTOT 4096   // (T+1)*B rows
#define LDP 2560    // fused precompute row stride (AA + EE)

// ---------------- device scratch (static, no allocs) ----------------
__device__ float g_c    [BB*HH];
__device__ float g_pre  [MTOT*LDP];    // [t][b][0:2048]=attnx, [2048:2560]=attdx
__device__ float g_alogp[4*BB*AA];     // attn-logit split-K partials (z=4)
__device__ float g_x2p  [16*BB*EE];    // x2 partials (z=16)
__device__ float g_gp   [8*BB*H4];     // gate partials (z=8)
__device__ float g_bias2560[LDP];      // [0]*2048 | b_attd

// bf16 split activation buffers
__device__ __nv_bfloat16 g_xs_hi [MTOT*EE], g_xs_lo [MTOT*EE];
__device__ __nv_bfloat16 g_hid_hi[MTOT*HH], g_hid_lo[MTOT*HH];
__device__ __nv_bfloat16 g_xh_hi [BB*1024], g_xh_lo [BB*1024];   // [x2|h]
__device__ __nv_bfloat16 g_att_hi[BB*AA],   g_att_lo[BB*AA];

// bf16 split weights
__device__ __nv_bfloat16 g_Woh[VV*HH],   g_Wol[VV*HH];     // W_out
__device__ __nv_bfloat16 g_Wprh[LDP*EE], g_Wprl[LDP*EE];   // [W_attn_x ; W_attd_x]
__device__ __nv_bfloat16 g_Wn2h[AA*HH],  g_Wn2l[AA*HH];    // W_attn h-part
__device__ __nv_bfloat16 g_Wd2h[EE*AA],  g_Wd2l[EE*AA];    // W_attd a-part
__device__ __nv_bfloat16 g_Wch[H4*1024], g_Wcl[H4*1024];   // [W_ih|W_hh]

// ================= warp-MMA helpers (sm_80+ baseline PTX only) =================
__device__ __forceinline__ uint32_t smem_u32(const void* p) {
    uint32_t a;
    asm("{ .reg .u64 t; cvta.to.shared.u64 t, %1; cvt.u32.u64 %0, t; }" : "=r"(a) : "l"(p));
    return a;
}
__device__ __forceinline__ uint32_t sw128(uint32_t b) { return b ^ ((b >> 3) & 0x70); }

__device__ __forceinline__ void ldsm_x4(uint32_t* r, uint32_t addr) {
    asm volatile("ldmatrix.sync.aligned.m8n8.x4.shared.b16 {%0,%1,%2,%3}, [%4];"
                 : "=r"(r[0]), "=r"(r[1]), "=r"(r[2]), "=r"(r[3]) : "r"(addr));
}
__device__ __forceinline__ void ldsm_x2(uint32_t* r, uint32_t addr) {
    asm volatile("ldmatrix.sync.aligned.m8n8.x2.shared.b16 {%0,%1}, [%2];"
                 : "=r"(r[0]), "=r"(r[1]) : "r"(addr));
}
__device__ __forceinline__ void mma16816(float* d, const uint32_t* a, const uint32_t* b) {
    asm volatile("mma.sync.aligned.m16n8k16.row.col.f32.bf16.bf16.f32 "
                 "{%0,%1,%2,%3}, {%4,%5,%6,%7}, {%8,%9}, {%0,%1,%2,%3};"
                 : "+f"(d[0]), "+f"(d[1]), "+f"(d[2]), "+f"(d[3])
                 : "r"(a[0]), "r"(a[1]), "r"(a[2]), "r"(a[3]), "r"(b[0]), "r"(b[1]));
}
__device__ __forceinline__ void cpasync16(uint32_t dst, const void* src, int sz) {
    asm volatile("cp.async.cg.shared.global [%0], [%1], 16, %2;"
                 :: "r"(dst), "l"(src), "r"(sz));
}
#define CP_COMMIT() asm volatile("cp.async.commit_group;" ::: "memory")
#define CP_WAIT1()  asm volatile("cp.async.wait_group 1;" ::: "memory")
#define CP_WAIT0()  asm volatile("cp.async.wait_group 0;" ::: "memory")

__device__ __forceinline__ void split_write(float x, __nv_bfloat16* hi, __nv_bfloat16* lo, size_t i) {
    __nv_bfloat16 h = __float2bfloat16(x);
    hi[i] = h;
    lo[i] = __float2bfloat16(x - __bfloat162float(h));
}
__device__ __forceinline__ float sigmoidf_(float x) {
    return 1.0f / (1.0f + expf(-x));
}

// ============ MMA core: 128x128 tile over loaded smem ============
// smem buf layout: Ahi@0, Alo@16K, Bhi@32K, Blo@48K
__device__ __forceinline__ void mma_passes(uint32_t sb, float acc[4][4][4],
                                           int warp_m, int warp_n, int lane)
{
    #pragma unroll
    for (int pass = 0; pass < 3; pass++) {
        const uint32_t abase = sb + ((pass == 2) ? 16384 : 0);
        const uint32_t bbase = sb + 32768 + ((pass == 1) ? 16384 : 0);
        #pragma unroll
        for (int kk = 0; kk < 4; kk++) {
            uint32_t afr[4][4];
            #pragma unroll
            for (int mt = 0; mt < 4; mt++) {
                int row = warp_m * 64 + mt * 16 + (lane & 15);
                int kb  = kk * 32 + ((lane >> 4) << 4);
                ldsm_x4(afr[mt], abase + sw128(row * 128 + kb));
            }
            uint32_t bfr[4][2];
            #pragma unroll
            for (int nt = 0; nt < 4; nt++) {
                int row = warp_n * 32 + nt * 8 + (lane & 7);
                int kb  = kk * 32 + (((lane >> 3) & 1) << 4);
                ldsm_x2(bfr[nt], bbase + sw128(row * 128 + kb));
            }
            #pragma unroll
            for (int mt = 0; mt < 4; mt++)
                #pragma unroll
                for (int nt = 0; nt < 4; nt++)
                    mma16816(acc[mt][nt], afr[mt], bfr[nt]);
        }
    }
}

// ============ big warp-MMA split-bf16 GEMM, cp.async double-buffered ============
// A: [M x K] hi/lo, M mult of 128; B: [Ntot x K] hi/lo (row-guarded); K mult of 64.
__global__ void __launch_bounds__(256, 1)
gemm_mma_kernel(const __nv_bfloat16* __restrict__ Ahi,
                const __nv_bfloat16* __restrict__ Alo,
                const __nv_bfloat16* __restrict__ Bhi,
                const __nv_bfloat16* __restrict__ Blo,
                const float* __restrict__ bias,
                float* __restrict__ C, int ldc, int Ntot, int K)
{
    extern __shared__ char smem[];
    const uint32_t sb = smem_u32(smem);
    const int tid = threadIdx.x;
    const int wid = tid >> 5;
    const int lane = tid & 31;
    const int warp_m = wid & 1;
    const int warp_n = wid >> 1;
    const int bm = blockIdx.y * 128;
    const int bn = blockIdx.x * 128;

    float acc[4][4][4];
    #pragma unroll
    for (int i = 0; i < 4; i++)
        #pragma unroll
        for (int j = 0; j < 4; j++)
            #pragma unroll
            for (int r = 0; r < 4; r++) acc[i][j][r] = 0.0f;

    const __nv_bfloat16* srcs[4] = {Ahi, Alo, Bhi, Blo};
    const int nchunks = K >> 6;

    auto issue = [&](int kc, int buf) {
        const uint32_t bufbase = sb + buf * 65536;
        #pragma unroll
        for (int t = 0; t < 4; t++) {
            const __nv_bfloat16* src = srcs[t];
            const uint32_t dstbase = bufbase + t * 16384;
            #pragma unroll
            for (int j = 0; j < 4; j++) {
                int v = tid + j * 256;
                int row = v >> 3, c8 = v & 7;
                int sz = 16;
                const __nv_bfloat16* sp;
                if (t < 2) {
                    sp = src + (size_t)(bm + row) * K + kc * 64 + c8 * 8;
                } else {
                    int gn = bn + row;
                    if (gn >= Ntot) { gn = 0; sz = 0; }
                    sp = src + (size_t)gn * K + kc * 64 + c8 * 8;
                }
                cpasync16(dstbase + sw128(row * 128 + c8 * 16), sp, sz);
            }
        }
    };

    issue(0, 0);
    CP_COMMIT();

    for (int kc = 0; kc < nchunks; kc++) {
        const int buf = kc & 1;
        if (kc + 1 < nchunks) {
            issue(kc + 1, buf ^ 1);
            CP_COMMIT();
            CP_WAIT1();
        } else {
            CP_WAIT0();
        }
        __syncthreads();
        mma_passes(sb + buf * 65536, acc, warp_m, warp_n, lane);
        __syncthreads();
    }

    const int gid = lane >> 2;
    const int tg  = lane & 3;
    #pragma unroll
    for (int mt = 0; mt < 4; mt++) {
        int row0 = bm + warp_m * 64 + mt * 16 + gid;
        #pragma unroll
        for (int nt = 0; nt < 4; nt++) {
            int col = bn + warp_n * 32 + nt * 8 + tg * 2;
            if (col < Ntot) {
                float b0 = bias ? bias[col] : 0.0f;
                float b1 = bias ? bias[col + 1] : 0.0f;
                float2 v0 = make_float2(acc[mt][nt][0] + b0, acc[mt][nt][1] + b1);
                float2 v1 = make_float2(acc[mt][nt][2] + b0, acc[mt][nt][3] + b1);
                *(float2*)(C + (size_t)row0 * ldc + col) = v0;
                *(float2*)(C + (size_t)(row0 + 8) * ldc + col) = v1;
            }
        }
    }
}

// ============ step warp-MMA GEMM: M=128, split-K, cp.async double-buffered ============
// A rows 0..127 (lda); B rows bn..bn+127 (ldb); no guards (exact dims).
__global__ void __launch_bounds__(256, 1)
gemm_mma_step(const __nv_bfloat16* __restrict__ Ahi,
              const __nv_bfloat16* __restrict__ Alo, int lda,
              const __nv_bfloat16* __restrict__ Bhi,
              const __nv_bfloat16* __restrict__ Blo, int ldb,
              float* __restrict__ Cpart, int N, size_t pstride, int Kchunk)
{
    extern __shared__ char smem[];
    const uint32_t sb = smem_u32(smem);
    const int tid = threadIdx.x;
    const int wid = tid >> 5;
    const int lane = tid & 31;
    const int warp_m = wid & 1;
    const int warp_n = wid >> 1;
    const int bn = blockIdx.x * 128;
    const int kb = blockIdx.z * Kchunk;
    float* C = Cpart + (size_t)blockIdx.z * pstride;

    float acc[4][4][4];
    #pragma unroll
    for (int i = 0; i < 4; i++)
        #pragma unroll
        for (int j = 0; j < 4; j++)
            #pragma unroll
            for (int r = 0; r < 4; r++) acc[i][j][r] = 0.0f;

    const int nchunks = Kchunk >> 6;

    auto issue = [&](int kc, int buf) {
        const uint32_t bufbase = sb + buf * 65536;
        #pragma unroll
        for (int t = 0; t < 4; t++) {
            const __nv_bfloat16* src = (t == 0) ? Ahi : (t == 1) ? Alo : (t == 2) ? Bhi : Blo;
            const int rowbase = (t < 2) ? 0 : bn;
            const int ld = (t < 2) ? lda : ldb;
            const uint32_t dstbase = bufbase + t * 16384;
            #pragma unroll
            for (int j = 0; j < 4; j++) {
                int v = tid + j * 256;
                int row = v >> 3, c8 = v & 7;
                const __nv_bfloat16* sp = src + (size_t)(rowbase + row) * ld + kb + kc * 64 + c8 * 8;
                cpasync16(dstbase + sw128(row * 128 + c8 * 16), sp, 16);
            }
        }
    };

    issue(0, 0);
    CP_COMMIT();

    for (int kc = 0; kc < nchunks; kc++) {
        const int buf = kc & 1;
        if (kc + 1 < nchunks) {
            issue(kc + 1, buf ^ 1);
            CP_COMMIT();
            CP_WAIT1();
        } else {
            CP_WAIT0();
        }
        __syncthreads();
        mma_passes(sb + buf * 65536, acc, warp_m, warp_n, lane);
        __syncthreads();
    }

    const int gid = lane >> 2;
    const int tg  = lane & 3;
    #pragma unroll
    for (int mt = 0; mt < 4; mt++) {
        int row0 = warp_m * 64 + mt * 16 + gid;
        #pragma unroll
        for (int nt = 0; nt < 4; nt++) {
            int col = bn + warp_n * 32 + nt * 8 + tg * 2;
            *(float2*)(C + (size_t)row0 * N + col) =
                make_float2(acc[mt][nt][0], acc[mt][nt][1]);
            *(float2*)(C + (size_t)(row0 + 8) * N + col) =
                make_float2(acc[mt][nt][2], acc[mt][nt][3]);
        }
    }
}

// ================= setup / pointwise kernels =================

// xs split + xh init + c init, one kernel
__global__ void build_xs_kernel(const float* __restrict__ features,
                                const int*   __restrict__ captions,
                                const float* __restrict__ table,
                                __nv_bfloat16* __restrict__ hi,
                                __nv_bfloat16* __restrict__ lo,
                                __nv_bfloat16* __restrict__ xh_hi,
                                __nv_bfloat16* __restrict__ xh_lo,
                                float* __restrict__ c)
{
    int idx = blockIdx.x * blockDim.x + threadIdx.x;
    if (idx < MTOT * EE) {
        int e = idx % EE;
        int b = (idx / EE) % BB;
        int t = idx / (EE * BB);
        float v;
        if (t == 0) v = features[b * EE + e];
        else {
            int tok = captions[b * TT + (t - 1)];
            v = table[tok * EE + e];
        }
        split_write(v, hi, lo, idx);
        return;
    }
    idx -= MTOT * EE;
    if (idx < BB * 1024) {
        int b = idx / 1024, k = idx % 1024;
        float v = (k < 512) ? features[b * 512 + k] : 0.0f;
        split_write(v, xh_hi, xh_lo, idx);
        return;
    }
    idx -= BB * 1024;
    if (idx < BB * HH) c[idx] = 0.0f;
}

// all weight splits + wcat + bias2560, one kernel
#define S1SZ (AA*EE)      // W_attn x-part -> Wpr rows 0..2047
#define S2SZ (AA*HH)      // W_attn h-part -> Wn2
#define S3SZ (EE*EE)      // W_attd x-part -> Wpr rows 2048..2559
#define S4SZ (EE*AA)      // W_attd a-part -> Wd2
#define S5SZ (VV*HH)      // W_out -> Wo
#define S6SZ (H4*1024)    // Wcat
#define S7SZ (LDP)        // bias2560
__global__ void convert_all_kernel(const float* __restrict__ W_attn,
                                   const float* __restrict__ W_attd,
                                   const float* __restrict__ W_out,
                                   const float* __restrict__ Wih,
                                   const float* __restrict__ Whh,
                                   const float* __restrict__ b_attd,
                                   __nv_bfloat16* __restrict__ Wprh, __nv_bfloat16* __restrict__ Wprl,
                                   __nv_bfloat16* __restrict__ Wn2h, __nv_bfloat16* __restrict__ Wn2l,
                                   __nv_bfloat16* __restrict__ Wd2h, __nv_bfloat16* __restrict__ Wd2l,
                                   __nv_bfloat16* __restrict__ Woh,  __nv_bfloat16* __restrict__ Wol,
                                   __nv_bfloat16* __restrict__ Wch,  __nv_bfloat16* __restrict__ Wcl,
                                   float* __restrict__ bias2560)
{
    int idx = blockIdx.x * blockDim.x + threadIdx.x;
    if (idx < S1SZ) {
        int r = idx / EE, cc = idx % EE;
        split_write(W_attn[(size_t)r * 1024 + cc], Wprh, Wprl, idx);
        return;
    }
    idx -= S1SZ;
    if (idx < S2SZ) {
        int r = idx / HH, cc = idx % HH;
        split_write(W_attn[(size_t)r * 1024 + EE + cc], Wn2h, Wn2l, idx);
        return;
    }
    idx -= S2SZ;
    if (idx < S3SZ) {
        int r = idx / EE, cc = idx % EE;
        split_write(W_attd[(size_t)r * 2560 + cc], Wprh, Wprl, (size_t)(2048 + r) * EE + cc);
        return;
    }
    idx -= S3SZ;
    if (idx < S4SZ) {
        int r = idx / AA, cc = idx % AA;
        split_write(W_attd[(size_t)r * 2560 + EE + cc], Wd2h, Wd2l, idx);
        return;
    }
    idx -= S4SZ;
    if (idx < S5SZ) {
        split_write(W_out[idx], Woh, Wol, idx);
        return;
    }
    idx -= S5SZ;
    if (idx < S6SZ) {
        int n = idx / 1024, k = idx % 1024;
        float v = (k < 512) ? Wih[n * 512 + k] : Whh[n * 512 + (k - 512)];
        split_write(v, Wch, Wcl, idx);
        return;
    }
    idx -= S6SZ;
    if (idx < S7SZ) {
        bias2560[idx] = (idx < AA) ? 0.0f : b_attd[idx - AA];
    }
}

// softmax over 2048 (4 partials + attnx(pre,LDP) + bias), attend, write bf16 hi/lo
__global__ void softmax_attend_kernel(const float* __restrict__ parts,
                                      const float* __restrict__ pre_t,  // ld LDP
                                      const float* __restrict__ b_attn,
                                      const float* __restrict__ cnn,
                                      __nv_bfloat16* __restrict__ att_hi,
                                      __nv_bfloat16* __restrict__ att_lo)
{
    const int b = blockIdx.x;
    const int tid = threadIdx.x;     // 256
    __shared__ float red[256];

    float v[8];
    float mx = -1e30f;
    #pragma unroll
    for (int j = 0; j < 8; j++) {
        int col = tid + j * 256;
        size_t o = (size_t)b * AA + col;
        float s = pre_t[(size_t)b * LDP + col] + b_attn[col];
        #pragma unroll
        for (int p = 0; p < 4; p++) s += parts[(size_t)p * BB * AA + o];
        v[j] = s;
        mx = fmaxf(mx, s);
    }
    red[tid] = mx;
    __syncthreads();
    for (int s = 128; s > 0; s >>= 1) {
        if (tid < s) red[tid] = fmaxf(red[tid], red[tid + s]);
        __syncthreads();
    }
    mx = red[0];
    __syncthreads();

    float sum = 0.0f;
    #pragma unroll
    for (int j = 0; j < 8; j++) { v[j] = expf(v[j] - mx); sum += v[j]; }
    red[tid] = sum;
    __syncthreads();
    for (int s = 128; s > 0; s >>= 1) {
        if (tid < s) red[tid] += red[tid + s];
        __syncthreads();
    }
    float inv = 1.0f / red[0];

    #pragma unroll
    for (int j = 0; j < 8; j++) {
        int col = tid + j * 256;
        size_t o = (size_t)b * AA + col;
        split_write(cnn[o] * v[j] * inv, att_hi, att_lo, o);
    }
}

// x2 = sum of 16 partials + attdx(pre_t+2048, ld LDP) -> xh[:, :512] bf16 hi/lo
__global__ void combine_x2_kernel(const float* __restrict__ parts,
                                  const float* __restrict__ pre_t,
                                  __nv_bfloat16* __restrict__ xh_hi,
                                  __nv_bfloat16* __restrict__ xh_lo)
{
    int idx = blockIdx.x * blockDim.x + threadIdx.x;
    if (idx >= BB * EE) return;
    int b = idx / EE, e = idx % EE;
    float s = pre_t[(size_t)b * LDP + 2048 + e];
    #pragma unroll
    for (int p = 0; p < 16; p++) s += parts[(size_t)p * BB * EE + idx];
    split_write(s, xh_hi, xh_lo, (size_t)b * 1024 + e);
}

// LSTM pointwise: combine 8 gate partials + biases; update c; write h
__global__ void lstm_pointwise_kernel(const float* __restrict__ gp,
                                      const float* __restrict__ b_ih,
                                      const float* __restrict__ b_hh,
                                      __nv_bfloat16* __restrict__ xh_hi,
                                      __nv_bfloat16* __restrict__ xh_lo,
                                      float* __restrict__ c,
                                      __nv_bfloat16* __restrict__ hid_hi,
                                      __nv_bfloat16* __restrict__ hid_lo)
{
    int idx = blockIdx.x * blockDim.x + threadIdx.x;
    if (idx >= BB * HH) return;
    int b = idx / HH, n = idx % HH;
    float gi = b_ih[n]        + b_hh[n];
    float gf = b_ih[512 + n]  + b_hh[512 + n];
    float gg = b_ih[1024 + n] + b_hh[1024 + n];
    float go = b_ih[1536 + n] + b_hh[1536 + n];
    #pragma unroll
    for (int p = 0; p < 8; p++) {
        const float* base = gp + (size_t)p * BB * H4 + (size_t)b * H4;
        gi += base[n];
        gf += base[512 + n];
        gg += base[1024 + n];
        go += base[1536 + n];
    }
    gi = sigmoidf_(gi);
    gf = sigmoidf_(gf);
    gg = tanhf(gg);
    go = sigmoidf_(go);
    float cc = gf * c[idx] + gi * gg;
    float hh = go * tanhf(cc);
    c[idx] = cc;
    split_write(hh, xh_hi, xh_lo, (size_t)b * 1024 + 512 + n);
    split_write(hh, hid_hi, hid_lo, idx);
}

// ---------------- host ----------------

extern "C" void kernel_launch(void* const* d_in, const int* in_sizes, int n_in,
                              void* d_out, int out_size)
{
    const float* features = (const float*)d_in[0];
    const float* cnn      = (const float*)d_in[1];
    const int*   captions = (const int*)  d_in[2];
    const float* table    = (const float*)d_in[4];
    const float* W_ih     = (const float*)d_in[5];
    const float* W_hh     = (const float*)d_in[6];
    const float* b_ih     = (const float*)d_in[7];
    const float* b_hh     = (const float*)d_in[8];
    const float* W_attn   = (const float*)d_in[9];
    const float* b_attn   = (const float*)d_in[10];
    const float* W_attd   = (const float*)d_in[11];
    const float* b_attd   = (const float*)d_in[12];
    const float* W_out    = (const float*)d_in[13];
    const float* b_out    = (const float*)d_in[14];
    float* out = (float*)d_out;

    float *p_c, *p_pre, *p_alogp, *p_x2p, *p_gp, *p_b2560;
    __nv_bfloat16 *p_xsh, *p_xsl, *p_hih, *p_hil, *p_xhh, *p_xhl, *p_ath, *p_atl,
                  *p_Woh, *p_Wol, *p_Wprh, *p_Wprl, *p_Wn2h, *p_Wn2l,
                  *p_Wd2h, *p_Wd2l, *p_Wch, *p_Wcl;
    cudaGetSymbolAddress((void**)&p_c,     g_c);
    cudaGetSymbolAddress((void**)&p_pre,   g_pre);
    cudaGetSymbolAddress((void**)&p_alogp, g_alogp);
    cudaGetSymbolAddress((void**)&p_x2p,   g_x2p);
    cudaGetSymbolAddress((void**)&p_gp,    g_gp);
    cudaGetSymbolAddress((void**)&p_b2560, g_bias2560);
    cudaGetSymbolAddress((void**)&p_xsh,   g_xs_hi);
    cudaGetSymbolAddress((void**)&p_xsl,   g_xs_lo);
    cudaGetSymbolAddress((void**)&p_hih,   g_hid_hi);
    cudaGetSymbolAddress((void**)&p_hil,   g_hid_lo);
    cudaGetSymbolAddress((void**)&p_xhh,   g_xh_hi);
    cudaGetSymbolAddress((void**)&p_xhl,   g_xh_lo);
    cudaGetSymbolAddress((void**)&p_ath,   g_att_hi);
    cudaGetSymbolAddress((void**)&p_atl,   g_att_lo);
    cudaGetSymbolAddress((void**)&p_Woh,   g_Woh);
    cudaGetSymbolAddress((void**)&p_Wol,   g_Wol);
    cudaGetSymbolAddress((void**)&p_Wprh,  g_Wprh);
    cudaGetSymbolAddress((void**)&p_Wprl,  g_Wprl);
    cudaGetSymbolAddress((void**)&p_Wn2h,  g_Wn2h);
    cudaGetSymbolAddress((void**)&p_Wn2l,  g_Wn2l);
    cudaGetSymbolAddress((void**)&p_Wd2h,  g_Wd2h);
    cudaGetSymbolAddress((void**)&p_Wd2l,  g_Wd2l);
    cudaGetSymbolAddress((void**)&p_Wch,   g_Wch);
    cudaGetSymbolAddress((void**)&p_Wcl,   g_Wcl);

    cudaFuncSetAttribute(gemm_mma_kernel, cudaFuncAttributeMaxDynamicSharedMemorySize, 131072);
    cudaFuncSetAttribute(gemm_mma_step,   cudaFuncAttributeMaxDynamicSharedMemorySize, 131072);

    // ---- setup (2 kernels) ----
    {
        int total = MTOT * EE + BB * 1024 + BB * HH;
        build_xs_kernel<<<(total + 255) / 256, 256>>>(
            features, captions, table, p_xsh, p_xsl, p_xhh, p_xhl, p_c);
    }
    {
        long total = (long)S1SZ + S2SZ + S3SZ + S4SZ + S5SZ + S6SZ + S7SZ;
        convert_all_kernel<<<(int)((total + 255) / 256), 256>>>(
            W_attn, W_attd, W_out, W_ih, W_hh, b_attd,
            p_Wprh, p_Wprl, p_Wn2h, p_Wn2l, p_Wd2h, p_Wd2l,
            p_Woh, p_Wol, p_Wch, p_Wcl, p_b2560);
    }

    // ---- fused precompute: [attnx | attdx] = xs @ Wpr^T + [0|b_attd] ----
    gemm_mma_kernel<<<dim3(LDP / 128, MTOT / 128), 256, 131072>>>(
        p_xsh, p_xsl, p_Wprh, p_Wprl, p_b2560, p_pre, LDP, LDP, EE);

    // ---- t = 0: gates = [features|0] @ Wcat^T (split-K8), LSTM ----
    gemm_mma_step<<<dim3(H4 / 128, 1, 8), 256, 131072>>>(
        p_xhh, p_xhl, 1024, p_Wch, p_Wcl, 1024, p_gp, H4, (size_t)BB * H4, 128);
    lstm_pointwise_kernel<<<(BB * HH + 255) / 256, 256>>>(
        p_gp, b_ih, b_hh, p_xhh, p_xhl, p_c, p_hih, p_hil);

    // ---- recurrent loop (round-10 structure, double-buffered step GEMMs) ----
    for (int t = 1; t <= TT; t++) {
        float* pre_t = p_pre + (size_t)t * BB * LDP;

        // attn logits partials: h @ W_attn_h^T  (split-K4, K=512)
        gemm_mma_step<<<dim3(AA / 128, 1, 4), 256, 131072>>>(
            p_xhh + 512, p_xhl + 512, 1024, p_Wn2h, p_Wn2l, HH,
            p_alogp, AA, (size_t)BB * AA, 128);
        // softmax + attend -> att bf16
        softmax_attend_kernel<<<BB, 256>>>(p_alogp, pre_t, b_attn, cnn, p_ath, p_atl);
        // x2 partials: att @ W_attd_a^T  (split-K16, K=2048)
        gemm_mma_step<<<dim3(EE / 128, 1, 16), 256, 131072>>>(
            p_ath, p_atl, AA, p_Wd2h, p_Wd2l, AA,
            p_x2p, EE, (size_t)BB * EE, 128);
        // combine -> xh[:, :512] bf16
        combine_x2_kernel<<<(BB * EE + 255) / 256, 256>>>(p_x2p, pre_t, p_xhh, p_xhl);
        // gates partials: [x2|h] @ Wcat^T  (split-K8, K=1024)
        gemm_mma_step<<<dim3(H4 / 128, 1, 8), 256, 131072>>>(
            p_xhh, p_xhl, 1024, p_Wch, p_Wcl, 1024, p_gp, H4, (size_t)BB * H4, 128);
        // LSTM pointwise
        lstm_pointwise_kernel<<<(BB * HH + 255) / 256, 256>>>(
            p_gp, b_ih, b_hh, p_xhh, p_xhl, p_c,
            p_hih + (size_t)t * BB * HH, p_hil + (size_t)t * BB * HH);
    }

    // ---- output projection: logits = hidden @ W_out^T + b_out ----
    gemm_mma_kernel<<<dim3((VV + 127) / 128, MTOT / 128), 256, 131072>>>(
        p_hih, p_hil, p_Woh, p_Wol, b_out, out, VV, VV, HH);
}

// round 14
// speedup vs baseline: 1.6091x; 1.0781x over previous
#include <cuda_runtime.h>
#include <cuda_bf16.h>
#include <cuda_fp16.h>
#include <cstdint>
#include <math.h>

// Problem dims
#define BB  128
#define TT  31
#define TP1 32
#define EE  512
#define HH  512
#define H4  2048
#define VV  10000
#define AA  2048
#define MTOT 4096   // (T+1)*B rows
#define LDP 2560    // fused precompute row stride (AA + EE)

// ---------------- device scratch (static, no allocs) ----------------
__device__ float g_c    [BB*HH];
__device__ float g_pre  [MTOT*LDP];    // [t][b][0:2048]=attnx, [2048:2560]=attdx
__device__ float g_alogp[4*BB*AA];     // attn-logit split-K partials (z=4)
__device__ float g_x2p  [16*BB*EE];    // x2 partials (z=16)
__device__ float g_gp   [8*BB*H4];     // gate partials (z 0..3 = x-part, 4..7 = h-part)
__device__ float g_bias2560[LDP];      // [0]*2048 | b_attd

// bf16 split activation buffers (recurrent path, 3-pass precision)
__device__ __nv_bfloat16 g_xs_hi [MTOT*EE], g_xs_lo [MTOT*EE];
__device__ __nv_bfloat16 g_xh_hi [BB*1024], g_xh_lo [BB*1024];   // [x2|h]
__device__ __nv_bfloat16 g_att_hi[BB*AA],   g_att_lo[BB*AA];

// fp16 hidden history (output projection path, 2-pass precision)
__device__ __half g_hf_hi[MTOT*HH], g_hf_lo[MTOT*HH];
__device__ __half g_Wfh[VV*HH];                                  // W_out fp16 hi

// bf16 split weights
__device__ __nv_bfloat16 g_Wprh[LDP*EE], g_Wprl[LDP*EE];   // [W_attn_x ; W_attd_x]
__device__ __nv_bfloat16 g_Wn2h[AA*HH],  g_Wn2l[AA*HH];    // W_attn h-part
__device__ __nv_bfloat16 g_Wd2h[EE*AA],  g_Wd2l[EE*AA];    // W_attd a-part
__device__ __nv_bfloat16 g_Wch[H4*1024], g_Wcl[H4*1024];   // [W_ih|W_hh]

// ================= warp-MMA helpers (sm_80+ baseline PTX only) =================
__device__ __forceinline__ uint32_t smem_u32(const void* p) {
    uint32_t a;
    asm("{ .reg .u64 t; cvta.to.shared.u64 t, %1; cvt.u32.u64 %0, t; }" : "=r"(a) : "l"(p));
    return a;
}
__device__ __forceinline__ uint32_t sw128(uint32_t b) { return b ^ ((b >> 3) & 0x70); }

__device__ __forceinline__ void ldsm_x4(uint32_t* r, uint32_t addr) {
    asm volatile("ldmatrix.sync.aligned.m8n8.x4.shared.b16 {%0,%1,%2,%3}, [%4];"
                 : "=r"(r[0]), "=r"(r[1]), "=r"(r[2]), "=r"(r[3]) : "r"(addr));
}
__device__ __forceinline__ void ldsm_x2(uint32_t* r, uint32_t addr) {
    asm volatile("ldmatrix.sync.aligned.m8n8.x2.shared.b16 {%0,%1}, [%2];"
                 : "=r"(r[0]), "=r"(r[1]) : "r"(addr));
}
__device__ __forceinline__ void mma16816(float* d, const uint32_t* a, const uint32_t* b) {
    asm volatile("mma.sync.aligned.m16n8k16.row.col.f32.bf16.bf16.f32 "
                 "{%0,%1,%2,%3}, {%4,%5,%6,%7}, {%8,%9}, {%0,%1,%2,%3};"
                 : "+f"(d[0]), "+f"(d[1]), "+f"(d[2]), "+f"(d[3])
                 : "r"(a[0]), "r"(a[1]), "r"(a[2]), "r"(a[3]), "r"(b[0]), "r"(b[1]));
}
__device__ __forceinline__ void mma16816_f16(float* d, const uint32_t* a, const uint32_t* b) {
    asm volatile("mma.sync.aligned.m16n8k16.row.col.f32.f16.f16.f32 "
                 "{%0,%1,%2,%3}, {%4,%5,%6,%7}, {%8,%9}, {%0,%1,%2,%3};"
                 : "+f"(d[0]), "+f"(d[1]), "+f"(d[2]), "+f"(d[3])
                 : "r"(a[0]), "r"(a[1]), "r"(a[2]), "r"(a[3]), "r"(b[0]), "r"(b[1]));
}
__device__ __forceinline__ void cpasync16(uint32_t dst, const void* src, int sz) {
    asm volatile("cp.async.cg.shared.global [%0], [%1], 16, %2;"
                 :: "r"(dst), "l"(src), "r"(sz));
}
#define CP_COMMIT() asm volatile("cp.async.commit_group;" ::: "memory")
#define CP_WAIT1()  asm volatile("cp.async.wait_group 1;" ::: "memory")
#define CP_WAIT0()  asm volatile("cp.async.wait_group 0;" ::: "memory")

__device__ __forceinline__ void split_write(float x, __nv_bfloat16* hi, __nv_bfloat16* lo, size_t i) {
    __nv_bfloat16 h = __float2bfloat16(x);
    hi[i] = h;
    lo[i] = __float2bfloat16(x - __bfloat162float(h));
}
__device__ __forceinline__ float sigmoidf_(float x) {
    return 1.0f / (1.0f + expf(-x));
}

// ============ MMA cores over loaded smem ============
// bf16 3-pass; smem buf layout: Ahi@0, Alo@16K, Bhi@32K, Blo@48K
__device__ __forceinline__ void mma_passes(uint32_t sb, float acc[4][4][4],
                                           int warp_m, int warp_n, int lane)
{
    #pragma unroll
    for (int pass = 0; pass < 3; pass++) {
        const uint32_t abase = sb + ((pass == 2) ? 16384 : 0);
        const uint32_t bbase = sb + 32768 + ((pass == 1) ? 16384 : 0);
        #pragma unroll
        for (int kk = 0; kk < 4; kk++) {
            uint32_t afr[4][4];
            #pragma unroll
            for (int mt = 0; mt < 4; mt++) {
                int row = warp_m * 64 + mt * 16 + (lane & 15);
                int kb  = kk * 32 + ((lane >> 4) << 4);
                ldsm_x4(afr[mt], abase + sw128(row * 128 + kb));
            }
            uint32_t bfr[4][2];
            #pragma unroll
            for (int nt = 0; nt < 4; nt++) {
                int row = warp_n * 32 + nt * 8 + (lane & 7);
                int kb  = kk * 32 + (((lane >> 3) & 1) << 4);
                ldsm_x2(bfr[nt], bbase + sw128(row * 128 + kb));
            }
            #pragma unroll
            for (int mt = 0; mt < 4; mt++)
                #pragma unroll
                for (int nt = 0; nt < 4; nt++)
                    mma16816(acc[mt][nt], afr[mt], bfr[nt]);
        }
    }
}

// fp16 2-pass; smem buf layout: Ahi@0, Alo@16K, B@32K
__device__ __forceinline__ void mma_passes_f16(uint32_t sb, float acc[4][4][4],
                                               int warp_m, int warp_n, int lane)
{
    #pragma unroll
    for (int pass = 0; pass < 2; pass++) {
        const uint32_t abase = sb + pass * 16384;
        const uint32_t bbase = sb + 32768;
        #pragma unroll
        for (int kk = 0; kk < 4; kk++) {
            uint32_t afr[4][4];
            #pragma unroll
            for (int mt = 0; mt < 4; mt++) {
                int row = warp_m * 64 + mt * 16 + (lane & 15);
                int kb  = kk * 32 + ((lane >> 4) << 4);
                ldsm_x4(afr[mt], abase + sw128(row * 128 + kb));
            }
            uint32_t bfr[4][2];
            #pragma unroll
            for (int nt = 0; nt < 4; nt++) {
                int row = warp_n * 32 + nt * 8 + (lane & 7);
                int kb  = kk * 32 + (((lane >> 3) & 1) << 4);
                ldsm_x2(bfr[nt], bbase + sw128(row * 128 + kb));
            }
            #pragma unroll
            for (int mt = 0; mt < 4; mt++)
                #pragma unroll
                for (int nt = 0; nt < 4; nt++)
                    mma16816_f16(acc[mt][nt], afr[mt], bfr[nt]);
        }
    }
}

// ============ big warp-MMA split-bf16 GEMM (precompute), cp.async double-buffered ============
__global__ void __launch_bounds__(256, 1)
gemm_mma_kernel(const __nv_bfloat16* __restrict__ Ahi,
                const __nv_bfloat16* __restrict__ Alo,
                const __nv_bfloat16* __restrict__ Bhi,
                const __nv_bfloat16* __restrict__ Blo,
                const float* __restrict__ bias,
                float* __restrict__ C, int ldc, int Ntot, int K)
{
    extern __shared__ char smem[];
    const uint32_t sb = smem_u32(smem);
    const int tid = threadIdx.x;
    const int wid = tid >> 5;
    const int lane = tid & 31;
    const int warp_m = wid & 1;
    const int warp_n = wid >> 1;
    const int bm = blockIdx.y * 128;
    const int bn = blockIdx.x * 128;

    float acc[4][4][4];
    #pragma unroll
    for (int i = 0; i < 4; i++)
        #pragma unroll
        for (int j = 0; j < 4; j++)
            #pragma unroll
            for (int r = 0; r < 4; r++) acc[i][j][r] = 0.0f;

    const __nv_bfloat16* srcs[4] = {Ahi, Alo, Bhi, Blo};
    const int nchunks = K >> 6;

    auto issue = [&](int kc, int buf) {
        const uint32_t bufbase = sb + buf * 65536;
        #pragma unroll
        for (int t = 0; t < 4; t++) {
            const __nv_bfloat16* src = srcs[t];
            const uint32_t dstbase = bufbase + t * 16384;
            #pragma unroll
            for (int j = 0; j < 4; j++) {
                int v = tid + j * 256;
                int row = v >> 3, c8 = v & 7;
                int sz = 16;
                const __nv_bfloat16* sp;
                if (t < 2) {
                    sp = src + (size_t)(bm + row) * K + kc * 64 + c8 * 8;
                } else {
                    int gn = bn + row;
                    if (gn >= Ntot) { gn = 0; sz = 0; }
                    sp = src + (size_t)gn * K + kc * 64 + c8 * 8;
                }
                cpasync16(dstbase + sw128(row * 128 + c8 * 16), sp, sz);
            }
        }
    };

    issue(0, 0);
    CP_COMMIT();

    for (int kc = 0; kc < nchunks; kc++) {
        const int buf = kc & 1;
        if (kc + 1 < nchunks) {
            issue(kc + 1, buf ^ 1);
            CP_COMMIT();
            CP_WAIT1();
        } else {
            CP_WAIT0();
        }
        __syncthreads();
        mma_passes(sb + buf * 65536, acc, warp_m, warp_n, lane);
        __syncthreads();
    }

    const int gid = lane >> 2;
    const int tg  = lane & 3;
    #pragma unroll
    for (int mt = 0; mt < 4; mt++) {
        int row0 = bm + warp_m * 64 + mt * 16 + gid;
        #pragma unroll
        for (int nt = 0; nt < 4; nt++) {
            int col = bn + warp_n * 32 + nt * 8 + tg * 2;
            if (col < Ntot) {
                float b0 = bias ? bias[col] : 0.0f;
                float b1 = bias ? bias[col + 1] : 0.0f;
                float2 v0 = make_float2(acc[mt][nt][0] + b0, acc[mt][nt][1] + b1);
                float2 v1 = make_float2(acc[mt][nt][2] + b0, acc[mt][nt][3] + b1);
                *(float2*)(C + (size_t)row0 * ldc + col) = v0;
                *(float2*)(C + (size_t)(row0 + 8) * ldc + col) = v1;
            }
        }
    }
}

// ============ output GEMM: fp16 2-pass (A hi/lo, B hi only), cp.async double-buffered ============
__global__ void __launch_bounds__(256, 1)
gemm_f16_kernel(const __half* __restrict__ Ahi,
                const __half* __restrict__ Alo,
                const __half* __restrict__ B,
                const float* __restrict__ bias,
                float* __restrict__ C, int ldc, int Ntot, int K)
{
    extern __shared__ char smem[];
    const uint32_t sb = smem_u32(smem);
    const int tid = threadIdx.x;
    const int wid = tid >> 5;
    const int lane = tid & 31;
    const int warp_m = wid & 1;
    const int warp_n = wid >> 1;
    const int bm = blockIdx.y * 128;
    const int bn = blockIdx.x * 128;

    float acc[4][4][4];
    #pragma unroll
    for (int i = 0; i < 4; i++)
        #pragma unroll
        for (int j = 0; j < 4; j++)
            #pragma unroll
            for (int r = 0; r < 4; r++) acc[i][j][r] = 0.0f;

    const __half* srcs[3] = {Ahi, Alo, B};
    const int nchunks = K >> 6;

    auto issue = [&](int kc, int buf) {
        const uint32_t bufbase = sb + buf * 49152;
        #pragma unroll
        for (int t = 0; t < 3; t++) {
            const __half* src = srcs[t];
            const uint32_t dstbase = bufbase + t * 16384;
            #pragma unroll
            for (int j = 0; j < 4; j++) {
                int v = tid + j * 256;
                int row = v >> 3, c8 = v & 7;
                int sz = 16;
                const __half* sp;
                if (t < 2) {
                    sp = src + (size_t)(bm + row) * K + kc * 64 + c8 * 8;
                } else {
                    int gn = bn + row;
                    if (gn >= Ntot) { gn = 0; sz = 0; }
                    sp = src + (size_t)gn * K + kc * 64 + c8 * 8;
                }
                cpasync16(dstbase + sw128(row * 128 + c8 * 16), sp, sz);
            }
        }
    };

    issue(0, 0);
    CP_COMMIT();

    for (int kc = 0; kc < nchunks; kc++) {
        const int buf = kc & 1;
        if (kc + 1 < nchunks) {
            issue(kc + 1, buf ^ 1);
            CP_COMMIT();
            CP_WAIT1();
        } else {
            CP_WAIT0();
        }
        __syncthreads();
        mma_passes_f16(sb + buf * 49152, acc, warp_m, warp_n, lane);
        __syncthreads();
    }

    const int gid = lane >> 2;
    const int tg  = lane & 3;
    #pragma unroll
    for (int mt = 0; mt < 4; mt++) {
        int row0 = bm + warp_m * 64 + mt * 16 + gid;
        #pragma unroll
        for (int nt = 0; nt < 4; nt++) {
            int col = bn + warp_n * 32 + nt * 8 + tg * 2;
            if (col < Ntot) {
                float b0 = bias ? bias[col] : 0.0f;
                float b1 = bias ? bias[col + 1] : 0.0f;
                float2 v0 = make_float2(acc[mt][nt][0] + b0, acc[mt][nt][1] + b1);
                float2 v1 = make_float2(acc[mt][nt][2] + b0, acc[mt][nt][3] + b1);
                *(float2*)(C + (size_t)row0 * ldc + col) = v0;
                *(float2*)(C + (size_t)(row0 + 8) * ldc + col) = v1;
            }
        }
    }
}

// ============ step warp-MMA GEMM: M=128, split-K, cp.async double-buffered ============
__global__ void __launch_bounds__(256, 1)
gemm_mma_step(const __nv_bfloat16* __restrict__ Ahi,
              const __nv_bfloat16* __restrict__ Alo, int lda,
              const __nv_bfloat16* __restrict__ Bhi,
              const __nv_bfloat16* __restrict__ Blo, int ldb,
              float* __restrict__ Cpart, int N, size_t pstride, int Kchunk)
{
    extern __shared__ char smem[];
    const uint32_t sb = smem_u32(smem);
    const int tid = threadIdx.x;
    const int wid = tid >> 5;
    const int lane = tid & 31;
    const int warp_m = wid & 1;
    const int warp_n = wid >> 1;
    const int bn = blockIdx.x * 128;
    const int kb = blockIdx.z * Kchunk;
    float* C = Cpart + (size_t)blockIdx.z * pstride;

    float acc[4][4][4];
    #pragma unroll
    for (int i = 0; i < 4; i++)
        #pragma unroll
        for (int j = 0; j < 4; j++)
            #pragma unroll
            for (int r = 0; r < 4; r++) acc[i][j][r] = 0.0f;

    const int nchunks = Kchunk >> 6;

    auto issue = [&](int kc, int buf) {
        const uint32_t bufbase = sb + buf * 65536;
        #pragma unroll
        for (int t = 0; t < 4; t++) {
            const __nv_bfloat16* src = (t == 0) ? Ahi : (t == 1) ? Alo : (t == 2) ? Bhi : Blo;
            const int rowbase = (t < 2) ? 0 : bn;
            const int ld = (t < 2) ? lda : ldb;
            const uint32_t dstbase = bufbase + t * 16384;
            #pragma unroll
            for (int j = 0; j < 4; j++) {
                int v = tid + j * 256;
                int row = v >> 3, c8 = v & 7;
                const __nv_bfloat16* sp = src + (size_t)(rowbase + row) * ld + kb + kc * 64 + c8 * 8;
                cpasync16(dstbase + sw128(row * 128 + c8 * 16), sp, 16);
            }
        }
    };

    issue(0, 0);
    CP_COMMIT();

    for (int kc = 0; kc < nchunks; kc++) {
        const int buf = kc & 1;
        if (kc + 1 < nchunks) {
            issue(kc + 1, buf ^ 1);
            CP_COMMIT();
            CP_WAIT1();
        } else {
            CP_WAIT0();
        }
        __syncthreads();
        mma_passes(sb + buf * 65536, acc, warp_m, warp_n, lane);
        __syncthreads();
    }

    const int gid = lane >> 2;
    const int tg  = lane & 3;
    #pragma unroll
    for (int mt = 0; mt < 4; mt++) {
        int row0 = warp_m * 64 + mt * 16 + gid;
        #pragma unroll
        for (int nt = 0; nt < 4; nt++) {
            int col = bn + warp_n * 32 + nt * 8 + tg * 2;
            *(float2*)(C + (size_t)row0 * N + col) =
                make_float2(acc[mt][nt][0], acc[mt][nt][1]);
            *(float2*)(C + (size_t)(row0 + 8) * N + col) =
                make_float2(acc[mt][nt][2], acc[mt][nt][3]);
        }
    }
}

// ============ fused step link 1: alog (blocks 0..63) + gates_h (blocks 64..127) ============
// A = h (xh+512) both; N = 2048 both; K = 512 (Kchunk=128, kz = id&3, ntile = id>>2).
__global__ void __launch_bounds__(256, 1)
fused_alog_gatesh(const __nv_bfloat16* __restrict__ Ahi,
                  const __nv_bfloat16* __restrict__ Alo,
                  const __nv_bfloat16* __restrict__ B1hi,
                  const __nv_bfloat16* __restrict__ B1lo,   // Wn2, ldb 512
                  const __nv_bfloat16* __restrict__ B2hi,
                  const __nv_bfloat16* __restrict__ B2lo,   // Wch+512, ldb 1024
                  float* __restrict__ C1,                    // alogp
                  float* __restrict__ C2)                    // gp + 4*BB*H4
{
    extern __shared__ char smem[];
    const uint32_t sb = smem_u32(smem);
    const int tid = threadIdx.x;
    const int wid = tid >> 5;
    const int lane = tid & 31;
    const int warp_m = wid & 1;
    const int warp_n = wid >> 1;
    const bool isg = blockIdx.x >= 64;
    const int id = blockIdx.x & 63;
    const int bn = (id >> 2) * 128;
    const int kb = (id & 3) * 128;
    const __nv_bfloat16* Bhi = isg ? B2hi : B1hi;
    const __nv_bfloat16* Blo = isg ? B2lo : B1lo;
    const int ldb = isg ? 1024 : 512;
    float* C = (isg ? C2 : C1) + (size_t)(id & 3) * BB * 2048;

    float acc[4][4][4];
    #pragma unroll
    for (int i = 0; i < 4; i++)
        #pragma unroll
        for (int j = 0; j < 4; j++)
            #pragma unroll
            for (int r = 0; r < 4; r++) acc[i][j][r] = 0.0f;

    auto issue = [&](int kc, int buf) {
        const uint32_t bufbase = sb + buf * 65536;
        #pragma unroll
        for (int t = 0; t < 4; t++) {
            const __nv_bfloat16* src = (t == 0) ? Ahi : (t == 1) ? Alo : (t == 2) ? Bhi : Blo;
            const int rowbase = (t < 2) ? 0 : bn;
            const int ld = (t < 2) ? 1024 : ldb;
            const uint32_t dstbase = bufbase + t * 16384;
            #pragma unroll
            for (int j = 0; j < 4; j++) {
                int v = tid + j * 256;
                int row = v >> 3, c8 = v & 7;
                const __nv_bfloat16* sp = src + (size_t)(rowbase + row) * ld + kb + kc * 64 + c8 * 8;
                cpasync16(dstbase + sw128(row * 128 + c8 * 16), sp, 16);
            }
        }
    };

    issue(0, 0);
    CP_COMMIT();
    issue(1, 1);
    CP_COMMIT();
    CP_WAIT1();
    __syncthreads();
    mma_passes(sb, acc, warp_m, warp_n, lane);
    __syncthreads();
    CP_WAIT0();
    __syncthreads();
    mma_passes(sb + 65536, acc, warp_m, warp_n, lane);

    const int gid = lane >> 2;
    const int tg  = lane & 3;
    #pragma unroll
    for (int mt = 0; mt < 4; mt++) {
        int row0 = warp_m * 64 + mt * 16 + gid;
        #pragma unroll
        for (int nt = 0; nt < 4; nt++) {
            int col = bn + warp_n * 32 + nt * 8 + tg * 2;
            *(float2*)(C + (size_t)row0 * 2048 + col) =
                make_float2(acc[mt][nt][0], acc[mt][nt][1]);
            *(float2*)(C + (size_t)(row0 + 8) * 2048 + col) =
                make_float2(acc[mt][nt][2], acc[mt][nt][3]);
        }
    }
}

// ================= setup / pointwise kernels =================

// xs split + xh init + c init, one kernel
__global__ void build_xs_kernel(const float* __restrict__ features,
                                const int*   __restrict__ captions,
                                const float* __restrict__ table,
                                __nv_bfloat16* __restrict__ hi,
                                __nv_bfloat16* __restrict__ lo,
                                __nv_bfloat16* __restrict__ xh_hi,
                                __nv_bfloat16* __restrict__ xh_lo,
                                float* __restrict__ c)
{
    int idx = blockIdx.x * blockDim.x + threadIdx.x;
    if (idx < MTOT * EE) {
        int e = idx % EE;
        int b = (idx / EE) % BB;
        int t = idx / (EE * BB);
        float v;
        if (t == 0) v = features[b * EE + e];
        else {
            int tok = captions[b * TT + (t - 1)];
            v = table[tok * EE + e];
        }
        split_write(v, hi, lo, idx);
        return;
    }
    idx -= MTOT * EE;
    if (idx < BB * 1024) {
        int b = idx / 1024, k = idx % 1024;
        float v = (k < 512) ? features[b * 512 + k] : 0.0f;
        split_write(v, xh_hi, xh_lo, idx);
        return;
    }
    idx -= BB * 1024;
    if (idx < BB * HH) c[idx] = 0.0f;
}

// all weight splits + wcat + bias2560, one kernel
#define S1SZ (AA*EE)      // W_attn x-part -> Wpr rows 0..2047
#define S2SZ (AA*HH)      // W_attn h-part -> Wn2
#define S3SZ (EE*EE)      // W_attd x-part -> Wpr rows 2048..2559
#define S4SZ (EE*AA)      // W_attd a-part -> Wd2
#define S5SZ (VV*HH)      // W_out -> Wf (fp16 hi)
#define S6SZ (H4*1024)    // Wcat
#define S7SZ (LDP)        // bias2560
__global__ void convert_all_kernel(const float* __restrict__ W_attn,
                                   const float* __restrict__ W_attd,
                                   const float* __restrict__ W_out,
                                   const float* __restrict__ Wih,
                                   const float* __restrict__ Whh,
                                   const float* __restrict__ b_attd,
                                   __nv_bfloat16* __restrict__ Wprh, __nv_bfloat16* __restrict__ Wprl,
                                   __nv_bfloat16* __restrict__ Wn2h, __nv_bfloat16* __restrict__ Wn2l,
                                   __nv_bfloat16* __restrict__ Wd2h, __nv_bfloat16* __restrict__ Wd2l,
                                   __half* __restrict__ Wfh,
                                   __nv_bfloat16* __restrict__ Wch,  __nv_bfloat16* __restrict__ Wcl,
                                   float* __restrict__ bias2560)
{
    int idx = blockIdx.x * blockDim.x + threadIdx.x;
    if (idx < S1SZ) {
        int r = idx / EE, cc = idx % EE;
        split_write(W_attn[(size_t)r * 1024 + cc], Wprh, Wprl, idx);
        return;
    }
    idx -= S1SZ;
    if (idx < S2SZ) {
        int r = idx / HH, cc = idx % HH;
        split_write(W_attn[(size_t)r * 1024 + EE + cc], Wn2h, Wn2l, idx);
        return;
    }
    idx -= S2SZ;
    if (idx < S3SZ) {
        int r = idx / EE, cc = idx % EE;
        split_write(W_attd[(size_t)r * 2560 + cc], Wprh, Wprl, (size_t)(2048 + r) * EE + cc);
        return;
    }
    idx -= S3SZ;
    if (idx < S4SZ) {
        int r = idx / AA, cc = idx % AA;
        split_write(W_attd[(size_t)r * 2560 + EE + cc], Wd2h, Wd2l, idx);
        return;
    }
    idx -= S4SZ;
    if (idx < S5SZ) {
        Wfh[idx] = __float2half(W_out[idx]);
        return;
    }
    idx -= S5SZ;
    if (idx < S6SZ) {
        int n = idx / 1024, k = idx % 1024;
        float v = (k < 512) ? Wih[n * 512 + k] : Whh[n * 512 + (k - 512)];
        split_write(v, Wch, Wcl, idx);
        return;
    }
    idx -= S6SZ;
    if (idx < S7SZ) {
        bias2560[idx] = (idx < AA) ? 0.0f : b_attd[idx - AA];
    }
}

// softmax over 2048 (4 partials + attnx(pre,LDP) + bias), attend, write bf16 hi/lo
__global__ void softmax_attend_kernel(const float* __restrict__ parts,
                                      const float* __restrict__ pre_t,  // ld LDP
                                      const float* __restrict__ b_attn,
                                      const float* __restrict__ cnn,
                                      __nv_bfloat16* __restrict__ att_hi,
                                      __nv_bfloat16* __restrict__ att_lo)
{
    const int b = blockIdx.x;
    const int tid = threadIdx.x;     // 256
    __shared__ float red[256];

    float v[8];
    float mx = -1e30f;
    #pragma unroll
    for (int j = 0; j < 8; j++) {
        int col = tid + j * 256;
        size_t o = (size_t)b * AA + col;
        float s = pre_t[(size_t)b * LDP + col] + b_attn[col];
        #pragma unroll
        for (int p = 0; p < 4; p++) s += parts[(size_t)p * BB * AA + o];
        v[j] = s;
        mx = fmaxf(mx, s);
    }
    red[tid] = mx;
    __syncthreads();
    for (int s = 128; s > 0; s >>= 1) {
        if (tid < s) red[tid] = fmaxf(red[tid], red[tid + s]);
        __syncthreads();
    }
    mx = red[0];
    __syncthreads();

    float sum = 0.0f;
    #pragma unroll
    for (int j = 0; j < 8; j++) { v[j] = expf(v[j] - mx); sum += v[j]; }
    red[tid] = sum;
    __syncthreads();
    for (int s = 128; s > 0; s >>= 1) {
        if (tid < s) red[tid] += red[tid + s];
        __syncthreads();
    }
    float inv = 1.0f / red[0];

    #pragma unroll
    for (int j = 0; j < 8; j++) {
        int col = tid + j * 256;
        size_t o = (size_t)b * AA + col;
        split_write(cnn[o] * v[j] * inv, att_hi, att_lo, o);
    }
}

// x2 = sum of 16 partials + attdx(pre_t+2048, ld LDP) -> xh[:, :512] bf16 hi/lo
__global__ void combine_x2_kernel(const float* __restrict__ parts,
                                  const float* __restrict__ pre_t,
                                  __nv_bfloat16* __restrict__ xh_hi,
                                  __nv_bfloat16* __restrict__ xh_lo)
{
    int idx = blockIdx.x * blockDim.x + threadIdx.x;
    if (idx >= BB * EE) return;
    int b = idx / EE, e = idx % EE;
    float s = pre_t[(size_t)b * LDP + 2048 + e];
    #pragma unroll
    for (int p = 0; p < 16; p++) s += parts[(size_t)p * BB * EE + idx];
    split_write(s, xh_hi, xh_lo, (size_t)b * 1024 + e);
}

// LSTM pointwise: combine 8 gate partials + biases; update c; write h (bf16 xh + fp16 hid)
__global__ void lstm_pointwise_kernel(const float* __restrict__ gp,
                                      const float* __restrict__ b_ih,
                                      const float* __restrict__ b_hh,
                                      __nv_bfloat16* __restrict__ xh_hi,
                                      __nv_bfloat16* __restrict__ xh_lo,
                                      float* __restrict__ c,
                                      __half* __restrict__ hid_hi,
                                      __half* __restrict__ hid_lo)
{
    int idx = blockIdx.x * blockDim.x + threadIdx.x;
    if (idx >= BB * HH) return;
    int b = idx / HH, n = idx % HH;
    float gi = b_ih[n]        + b_hh[n];
    float gf = b_ih[512 + n]  + b_hh[512 + n];
    float gg = b_ih[1024 + n] + b_hh[1024 + n];
    float go = b_ih[1536 + n] + b_hh[1536 + n];
    #pragma unroll
    for (int p = 0; p < 8; p++) {
        const float* base = gp + (size_t)p * BB * H4 + (size_t)b * H4;
        gi += base[n];
        gf += base[512 + n];
        gg += base[1024 + n];
        go += base[1536 + n];
    }
    gi = sigmoidf_(gi);
    gf = sigmoidf_(gf);
    gg = tanhf(gg);
    go = sigmoidf_(go);
    float cc = gf * c[idx] + gi * gg;
    float hh = go * tanhf(cc);
    c[idx] = cc;
    split_write(hh, xh_hi, xh_lo, (size_t)b * 1024 + 512 + n);
    __half hf = __float2half(hh);
    hid_hi[idx] = hf;
    hid_lo[idx] = __float2half(hh - __half2float(hf));
}

// ---------------- host ----------------

extern "C" void kernel_launch(void* const* d_in, const int* in_sizes, int n_in,
                              void* d_out, int out_size)
{
    const float* features = (const float*)d_in[0];
    const float* cnn      = (const float*)d_in[1];
    const int*   captions = (const int*)  d_in[2];
    const float* table    = (const float*)d_in[4];
    const float* W_ih     = (const float*)d_in[5];
    const float* W_hh     = (const float*)d_in[6];
    const float* b_ih     = (const float*)d_in[7];
    const float* b_hh     = (const float*)d_in[8];
    const float* W_attn   = (const float*)d_in[9];
    const float* b_attn   = (const float*)d_in[10];
    const float* W_attd   = (const float*)d_in[11];
    const float* b_attd   = (const float*)d_in[12];
    const float* W_out    = (const float*)d_in[13];
    const float* b_out    = (const float*)d_in[14];
    float* out = (float*)d_out;

    float *p_c, *p_pre, *p_alogp, *p_x2p, *p_gp, *p_b2560;
    __nv_bfloat16 *p_xsh, *p_xsl, *p_xhh, *p_xhl, *p_ath, *p_atl,
                  *p_Wprh, *p_Wprl, *p_Wn2h, *p_Wn2l,
                  *p_Wd2h, *p_Wd2l, *p_Wch, *p_Wcl;
    __half *p_hfh, *p_hfl, *p_Wfh;
    cudaGetSymbolAddress((void**)&p_c,     g_c);
    cudaGetSymbolAddress((void**)&p_pre,   g_pre);
    cudaGetSymbolAddress((void**)&p_alogp, g_alogp);
    cudaGetSymbolAddress((void**)&p_x2p,   g_x2p);
    cudaGetSymbolAddress((void**)&p_gp,    g_gp);
    cudaGetSymbolAddress((void**)&p_b2560, g_bias2560);
    cudaGetSymbolAddress((void**)&p_xsh,   g_xs_hi);
    cudaGetSymbolAddress((void**)&p_xsl,   g_xs_lo);
    cudaGetSymbolAddress((void**)&p_xhh,   g_xh_hi);
    cudaGetSymbolAddress((void**)&p_xhl,   g_xh_lo);
    cudaGetSymbolAddress((void**)&p_ath,   g_att_hi);
    cudaGetSymbolAddress((void**)&p_atl,   g_att_lo);
    cudaGetSymbolAddress((void**)&p_hfh,   g_hf_hi);
    cudaGetSymbolAddress((void**)&p_hfl,   g_hf_lo);
    cudaGetSymbolAddress((void**)&p_Wfh,   g_Wfh);
    cudaGetSymbolAddress((void**)&p_Wprh,  g_Wprh);
    cudaGetSymbolAddress((void**)&p_Wprl,  g_Wprl);
    cudaGetSymbolAddress((void**)&p_Wn2h,  g_Wn2h);
    cudaGetSymbolAddress((void**)&p_Wn2l,  g_Wn2l);
    cudaGetSymbolAddress((void**)&p_Wd2h,  g_Wd2h);
    cudaGetSymbolAddress((void**)&p_Wd2l,  g_Wd2l);
    cudaGetSymbolAddress((void**)&p_Wch,   g_Wch);
    cudaGetSymbolAddress((void**)&p_Wcl,   g_Wcl);

    cudaFuncSetAttribute(gemm_mma_kernel,   cudaFuncAttributeMaxDynamicSharedMemorySize, 131072);
    cudaFuncSetAttribute(gemm_mma_step,     cudaFuncAttributeMaxDynamicSharedMemorySize, 131072);
    cudaFuncSetAttribute(fused_alog_gatesh, cudaFuncAttributeMaxDynamicSharedMemorySize, 131072);
    cudaFuncSetAttribute(gemm_f16_kernel,   cudaFuncAttributeMaxDynamicSharedMemorySize, 98304);

    // ---- setup (2 kernels) ----
    {
        int total = MTOT * EE + BB * 1024 + BB * HH;
        build_xs_kernel<<<(total + 255) / 256, 256>>>(
            features, captions, table, p_xsh, p_xsl, p_xhh, p_xhl, p_c);
    }
    {
        long total = (long)S1SZ + S2SZ + S3SZ + S4SZ + S5SZ + S6SZ + S7SZ;
        convert_all_kernel<<<(int)((total + 255) / 256), 256>>>(
            W_attn, W_attd, W_out, W_ih, W_hh, b_attd,
            p_Wprh, p_Wprl, p_Wn2h, p_Wn2l, p_Wd2h, p_Wd2l,
            p_Wfh, p_Wch, p_Wcl, p_b2560);
    }

    // ---- fused precompute: [attnx | attdx] = xs @ Wpr^T + [0|b_attd] ----
    gemm_mma_kernel<<<dim3(LDP / 128, MTOT / 128), 256, 131072>>>(
        p_xsh, p_xsl, p_Wprh, p_Wprl, p_b2560, p_pre, LDP, LDP, EE);

    // ---- t = 0: gates = [features|0] @ Wcat^T (split-K8), LSTM ----
    gemm_mma_step<<<dim3(H4 / 128, 1, 8), 256, 131072>>>(
        p_xhh, p_xhl, 1024, p_Wch, p_Wcl, 1024, p_gp, H4, (size_t)BB * H4, 128);
    lstm_pointwise_kernel<<<(BB * HH + 255) / 256, 256>>>(
        p_gp, b_ih, b_hh, p_xhh, p_xhl, p_c, p_hfh, p_hfl);

    // ---- recurrent loop: fused(alog+gatesh) -> softmax -> x2 -> combine -> gatesx -> lstm ----
    for (int t = 1; t <= TT; t++) {
        float* pre_t = p_pre + (size_t)t * BB * LDP;

        // (1) alog partials (z 0..3) + gates h-part partials (gp z 4..7), one launch
        fused_alog_gatesh<<<128, 256, 131072>>>(
            p_xhh + 512, p_xhl + 512,
            p_Wn2h, p_Wn2l, p_Wch + 512, p_Wcl + 512,
            p_alogp, p_gp + (size_t)4 * BB * H4);
        // (2) softmax + attend -> att bf16
        softmax_attend_kernel<<<BB, 256>>>(p_alogp, pre_t, b_attn, cnn, p_ath, p_atl);
        // (3) x2 partials: att @ W_attd_a^T  (split-K16, K=2048)
        gemm_mma_step<<<dim3(EE / 128, 1, 16), 256, 131072>>>(
            p_ath, p_atl, AA, p_Wd2h, p_Wd2l, AA,
            p_x2p, EE, (size_t)BB * EE, 128);
        // (4) combine -> xh[:, :512] bf16
        combine_x2_kernel<<<(BB * EE + 255) / 256, 256>>>(p_x2p, pre_t, p_xhh, p_xhl);
        // (5) gates x-part: x2 @ W_ih^T  (K=512, z 0..3)
        gemm_mma_step<<<dim3(H4 / 128, 1, 4), 256, 131072>>>(
            p_xhh, p_xhl, 1024, p_Wch, p_Wcl, 1024, p_gp, H4, (size_t)BB * H4, 128);
        // (6) LSTM pointwise (sums all 8 partials), writes bf16 xh-h + fp16 hid
        lstm_pointwise_kernel<<<(BB * HH + 255) / 256, 256>>>(
            p_gp, b_ih, b_hh, p_xhh, p_xhl, p_c,
            p_hfh + (size_t)t * BB * HH, p_hfl + (size_t)t * BB * HH);
    }

    // ---- output projection: logits = hidden @ W_out^T + b_out  (fp16 2-pass) ----
    gemm_f16_kernel<<<dim3((VV + 127) / 128, MTOT / 128), 256, 98304>>>(
        p_hfh, p_hfl, p_Wfh, b_out, out, VV, VV, HH);
}